// round 1
// baseline (speedup 1.0000x reference)
#include <cuda_runtime.h>
#include <math.h>

// ---------------- scratch (device globals: no allocation allowed) ----------
__device__ float g_bufA[4096 * 2048];
__device__ float g_bufB[4096 * 2048];
__device__ float g_x1v [4096 * 512];
__device__ float g_x2v [4096 * 512];
__device__ float g_scores[(size_t)4096 * 4096];
__device__ unsigned g_minkey;
__device__ unsigned g_maxkey;

// order-preserving float<->uint key (handles negatives)
__device__ __forceinline__ unsigned f2key(float f) {
    unsigned u = __float_as_uint(f);
    return (u & 0x80000000u) ? ~u : (u | 0x80000000u);
}
__device__ __forceinline__ float key2f(unsigned k) {
    unsigned u = (k & 0x80000000u) ? (k ^ 0x80000000u) : ~k;
    return __uint_as_float(u);
}

enum { ACT_NONE = 0, ACT_RELU = 1, ACT_SIG = 2 };

__device__ __forceinline__ float apply_act(float v, int act) {
    if (act == ACT_RELU) return fmaxf(v, 0.0f);
    if (act == ACT_SIG)  return 1.0f / (1.0f + expf(-v));
    return v;
}

// ---------------- main tiled SGEMM: C = act(A @ B^T + bias) ----------------
// A: [M,K] row-major; B: [N,K] row-major; C: [M,N] row-major.
// Requires M%128==0, N%128==0, K%16==0 (true for all layers here).
#define BM 128
#define BN 128
#define BK 16
#define TM 8
#define TN 8
#define LDP (BM + 4)   // padded row; 132 floats = 528B, 16B-aligned

template <int ACT, bool MINMAX, bool HASBIAS>
__global__ void __launch_bounds__(256)
gemm_nt(const float* __restrict__ A, const float* __restrict__ B,
        const float* __restrict__ bias, float* __restrict__ C,
        int M, int N, int K)
{
    __shared__ float As[BK][LDP];
    __shared__ float Bs[BK][LDP];

    const int tid = threadIdx.x;
    const int bm  = blockIdx.y * BM;
    const int bn  = blockIdx.x * BN;
    const int ty  = tid >> 4;   // 0..15
    const int tx  = tid & 15;   // 0..15

    float acc[TM][TN];
#pragma unroll
    for (int i = 0; i < TM; i++)
#pragma unroll
        for (int j = 0; j < TN; j++) acc[i][j] = 0.0f;

    for (int k0 = 0; k0 < K; k0 += BK) {
        // load 128x16 A-tile and B-tile, transposed into smem [k][row]
#pragma unroll
        for (int l = 0; l < 2; l++) {
            int f   = tid + l * 256;       // float4 index, 0..511
            int row = f >> 2;              // 0..127
            int c4  = (f & 3) << 2;        // 0,4,8,12
            float4 va = *(const float4*)&A[(size_t)(bm + row) * K + k0 + c4];
            As[c4 + 0][row] = va.x; As[c4 + 1][row] = va.y;
            As[c4 + 2][row] = va.z; As[c4 + 3][row] = va.w;
            float4 vb = *(const float4*)&B[(size_t)(bn + row) * K + k0 + c4];
            Bs[c4 + 0][row] = vb.x; Bs[c4 + 1][row] = vb.y;
            Bs[c4 + 2][row] = vb.z; Bs[c4 + 3][row] = vb.w;
        }
        __syncthreads();

#pragma unroll
        for (int k = 0; k < BK; k++) {
            float a[TM], b[TN];
#pragma unroll
            for (int i = 0; i < TM; i += 4) {
                float4 v = *(const float4*)&As[k][ty * TM + i];
                a[i] = v.x; a[i + 1] = v.y; a[i + 2] = v.z; a[i + 3] = v.w;
            }
#pragma unroll
            for (int j = 0; j < TN; j += 4) {
                float4 v = *(const float4*)&Bs[k][tx * TN + j];
                b[j] = v.x; b[j + 1] = v.y; b[j + 2] = v.z; b[j + 3] = v.w;
            }
#pragma unroll
            for (int i = 0; i < TM; i++)
#pragma unroll
                for (int j = 0; j < TN; j++)
                    acc[i][j] = fmaf(a[i], b[j], acc[i][j]);
        }
        __syncthreads();
    }

    // epilogue
    float lmin =  INFINITY;
    float lmax = -INFINITY;
#pragma unroll
    for (int i = 0; i < TM; i++) {
        int m = bm + ty * TM + i;
#pragma unroll
        for (int j = 0; j < TN; j += 4) {
            int n = bn + tx * TN + j;
            float4 v;
            float b0 = 0.f, b1 = 0.f, b2 = 0.f, b3 = 0.f;
            if (HASBIAS) {
                float4 bv = *(const float4*)&bias[n];
                b0 = bv.x; b1 = bv.y; b2 = bv.z; b3 = bv.w;
            }
            v.x = apply_act(acc[i][j + 0] + b0, ACT);
            v.y = apply_act(acc[i][j + 1] + b1, ACT);
            v.z = apply_act(acc[i][j + 2] + b2, ACT);
            v.w = apply_act(acc[i][j + 3] + b3, ACT);
            if (MINMAX) {
                lmin = fminf(lmin, fminf(fminf(v.x, v.y), fminf(v.z, v.w)));
                lmax = fmaxf(lmax, fmaxf(fmaxf(v.x, v.y), fmaxf(v.z, v.w)));
            }
            *(float4*)&C[(size_t)m * N + n] = v;
        }
    }

    if (MINMAX) {
        __shared__ float smin[256], smax[256];
        smin[tid] = lmin; smax[tid] = lmax;
        __syncthreads();
#pragma unroll
        for (int s = 128; s > 0; s >>= 1) {
            if (tid < s) {
                smin[tid] = fminf(smin[tid], smin[tid + s]);
                smax[tid] = fmaxf(smax[tid], smax[tid + s]);
            }
            __syncthreads();
        }
        if (tid == 0) {
            atomicMin(&g_minkey, f2key(smin[0]));
            atomicMax(&g_maxkey, f2key(smax[0]));
        }
    }
}

// ---------------- N=1 projection: out[m] = sigmoid(dot(A[m,:], w) + b) -----
template <int ACT>
__global__ void __launch_bounds__(256)
rowdot(const float* __restrict__ A, const float* __restrict__ w,
       const float* __restrict__ bias, float* __restrict__ out, int K)
{
    const int warp = threadIdx.x >> 5;
    const int lane = threadIdx.x & 31;
    const int row  = blockIdx.x * 8 + warp;
    const float* a = A + (size_t)row * K;
    float s = 0.0f;
    for (int k = lane * 4; k < K; k += 32 * 4) {
        float4 va = *(const float4*)&a[k];
        float4 vw = *(const float4*)&w[k];
        s += va.x * vw.x + va.y * vw.y + va.z * vw.z + va.w * vw.w;
    }
#pragma unroll
    for (int o = 16; o > 0; o >>= 1)
        s += __shfl_down_sync(0xffffffffu, s, o);
    if (lane == 0)
        out[row] = apply_act(s + bias[0], ACT);
}

// ---------------- min/max init + final rescale -----------------------------
__global__ void init_minmax_k() {
    g_minkey = 0xFFFFFFFFu;  // key for +inf side
    g_maxkey = 0x00000000u;
}

__global__ void __launch_bounds__(256)
scale_out(const float* __restrict__ s, float* __restrict__ out)
{
    float mn  = key2f(g_minkey);
    float mx  = key2f(g_maxkey);
    float inv = 1.0f / (mx - mn);
    size_t i = ((size_t)blockIdx.x * blockDim.x + threadIdx.x) * 4;
    float4 v = *(const float4*)&s[i];
    float4 o;
    o.x = (v.x - mn) * inv;
    o.y = (v.y - mn) * inv;
    o.z = (v.z - mn) * inv;
    o.w = (v.w - mn) * inv;
    *(float4*)&out[i] = o;
}

// ---------------- launch ----------------------------------------------------
static inline void launch_gemm(int act, bool hasbias, bool minmax,
                               const float* A, const float* B, const float* bias,
                               float* C, int M, int N, int K)
{
    dim3 grid(N / BN, M / BM);
    dim3 block(256);
    if (minmax) {
        gemm_nt<ACT_NONE, true, false><<<grid, block>>>(A, B, bias, C, M, N, K);
        return;
    }
    if (act == ACT_RELU)
        gemm_nt<ACT_RELU, false, true><<<grid, block>>>(A, B, bias, C, M, N, K);
    else if (act == ACT_SIG)
        gemm_nt<ACT_SIG, false, true><<<grid, block>>>(A, B, bias, C, M, N, K);
    else
        gemm_nt<ACT_NONE, false, true><<<grid, block>>>(A, B, bias, C, M, N, K);
}

extern "C" void kernel_launch(void* const* d_in, const int* in_sizes, int n_in,
                              void* d_out, int out_size)
{
    (void)in_sizes; (void)n_in; (void)out_size;
    const float* x1   = (const float*)d_in[0];
    const float* x2   = (const float*)d_in[1];
    const float* W1_1 = (const float*)d_in[2];   const float* b1_1 = (const float*)d_in[3];
    const float* W1_2 = (const float*)d_in[4];   const float* b1_2 = (const float*)d_in[5];
    const float* W1_3 = (const float*)d_in[6];   const float* b1_3 = (const float*)d_in[7];
    const float* W1_4 = (const float*)d_in[8];   const float* b1_4 = (const float*)d_in[9];
    const float* W1_5 = (const float*)d_in[10];  const float* b1_5 = (const float*)d_in[11];
    const float* Wp1  = (const float*)d_in[12];  const float* bp1  = (const float*)d_in[13];
    const float* W2_1 = (const float*)d_in[14];  const float* b2_1 = (const float*)d_in[15];
    const float* W2_2 = (const float*)d_in[16];  const float* b2_2 = (const float*)d_in[17];
    const float* W2_3 = (const float*)d_in[18];  const float* b2_3 = (const float*)d_in[19];
    const float* Wp2  = (const float*)d_in[20];  const float* bp2  = (const float*)d_in[21];

    float* out = (float*)d_out;
    const int B = 4096;
    const size_t NSC = (size_t)4096 * 4096;

    float *bufA, *bufB, *x1v, *x2v, *scores;
    cudaGetSymbolAddress((void**)&bufA,   g_bufA);
    cudaGetSymbolAddress((void**)&bufB,   g_bufB);
    cudaGetSymbolAddress((void**)&x1v,    g_x1v);
    cudaGetSymbolAddress((void**)&x2v,    g_x2v);
    cudaGetSymbolAddress((void**)&scores, g_scores);

    init_minmax_k<<<1, 1>>>();

    // branch 1
    launch_gemm(ACT_RELU, true, false, x1,   W1_1, b1_1, bufA, B, 2048, 1024);
    launch_gemm(ACT_RELU, true, false, bufA, W1_2, b1_2, bufB, B, 1024, 2048);
    launch_gemm(ACT_SIG,  true, false, bufB, W1_3, b1_3, x1v,  B,  512, 1024);
    launch_gemm(ACT_RELU, true, false, x1v,  W1_4, b1_4, bufA, B, 1024,  512);
    launch_gemm(ACT_RELU, true, false, bufA, W1_5, b1_5, bufB, B, 2048, 1024);
    rowdot<ACT_SIG><<<B / 8, 256>>>(bufB, Wp1, bp1, out + 0, 2048);           // pre_data

    // branch 2
    launch_gemm(ACT_RELU, true, false, x2,   W2_1, b2_1, bufA, B, 1024,  512);
    launch_gemm(ACT_SIG,  true, false, bufA, W2_2, b2_2, x2v,  B,  512, 1024);
    launch_gemm(ACT_RELU, true, false, x2v,  W2_3, b2_3, bufA, B, 1024,  512);
    rowdot<ACT_SIG><<<B / 8, 256>>>(bufA, Wp2, bp2, out + 4096 + NSC, 1024);  // pre_model

    // cross scores (+ fused global min/max)
    launch_gemm(ACT_NONE, false, true, x1v, x2v, nullptr, scores, B, 4096, 512);

    // min-max rescale -> pre_dm
    scale_out<<<(unsigned)(NSC / 4 / 256), 256>>>(scores, out + 4096);
}

// round 3
// speedup vs baseline: 2.3321x; 2.3321x over previous
#include <cuda_runtime.h>
#include <cuda_bf16.h>
#include <math.h>
#include <stdint.h>

typedef __nv_bfloat16 bf;

// ===================== device scratch (no allocation allowed) ==============
__device__ bf g_ahi[4096 * 2048];
__device__ bf g_alo[4096 * 2048];
__device__ bf g_bhi[4096 * 2048];
__device__ bf g_blo[4096 * 2048];
__device__ bf g_x1v_hi[4096 * 512];
__device__ bf g_x1v_lo[4096 * 512];
__device__ bf g_x2v_hi[4096 * 512];
__device__ bf g_x2v_lo[4096 * 512];
__device__ bf g_whi[8912896];
__device__ bf g_wlo[8912896];
__device__ bf g_inhi[6291456];
__device__ bf g_inlo[6291456];
__device__ float g_scores[(size_t)4096 * 4096];
__device__ unsigned g_minkey;
__device__ unsigned g_maxkey;

// weight pool offsets (elements)
#define OW11 0u
#define OW12 2097152u
#define OW13 4194304u
#define OW14 4718592u
#define OW15 5242880u
#define OW21 7340032u
#define OW22 7864320u
#define OW23 8388608u
#define OX1  0u
#define OX2  4194304u

// ===================== PTX helpers (sm_80-era, compiles for sm_103) ========
__device__ __forceinline__ uint32_t smem_to_u32(const void* p) {
    uint32_t a;
    asm("{ .reg .u64 t; cvta.to.shared.u64 t, %1; cvt.u32.u64 %0, t; }"
        : "=r"(a) : "l"(p));
    return a;
}

#define CP_ASYNC16(dst, src) \
    asm volatile("cp.async.cg.shared.global [%0], [%1], 16;" \
                 :: "r"(dst), "l"(src) : "memory")
#define CP_COMMIT() asm volatile("cp.async.commit_group;" ::: "memory")
#define CP_WAIT1()  asm volatile("cp.async.wait_group 1;" ::: "memory")
#define CP_WAIT0()  asm volatile("cp.async.wait_group 0;" ::: "memory")

#define LDSM_X4(r0, r1, r2, r3, addr) \
    asm volatile("ldmatrix.sync.aligned.m8n8.x4.shared.b16 {%0,%1,%2,%3}, [%4];" \
                 : "=r"(r0), "=r"(r1), "=r"(r2), "=r"(r3) : "r"(addr))

__device__ __forceinline__ void mma_bf16(float* c, uint32_t a0, uint32_t a1,
                                         uint32_t a2, uint32_t a3,
                                         uint32_t b0, uint32_t b1) {
    asm volatile(
        "mma.sync.aligned.m16n8k16.row.col.f32.bf16.bf16.f32 "
        "{%0,%1,%2,%3}, {%4,%5,%6,%7}, {%8,%9}, {%0,%1,%2,%3};"
        : "+f"(c[0]), "+f"(c[1]), "+f"(c[2]), "+f"(c[3])
        : "r"(a0), "r"(a1), "r"(a2), "r"(a3), "r"(b0), "r"(b1));
}

// ===================== misc helpers ========================================
__device__ __forceinline__ unsigned f2key(float f) {
    unsigned u = __float_as_uint(f);
    return (u & 0x80000000u) ? ~u : (u | 0x80000000u);
}
__device__ __forceinline__ float key2f(unsigned k) {
    unsigned u = (k & 0x80000000u) ? (k ^ 0x80000000u) : ~k;
    return __uint_as_float(u);
}
enum { ACT_NONE = 0, ACT_RELU = 1, ACT_SIG = 2 };
__device__ __forceinline__ float apply_act(float v, int act) {
    if (act == ACT_RELU) return fmaxf(v, 0.0f);
    if (act == ACT_SIG)  return 1.0f / (1.0f + expf(-v));
    return v;
}

// ===================== fp32 -> bf16 hi/lo split ============================
__global__ void __launch_bounds__(256)
split_f32(const float* __restrict__ in, bf* __restrict__ hi,
          bf* __restrict__ lo, int n)
{
    int i = (blockIdx.x * 256 + threadIdx.x) * 4;
    if (i >= n) return;
    float4 v = *(const float4*)(in + i);
    bf h0 = __float2bfloat16(v.x), h1 = __float2bfloat16(v.y);
    bf h2 = __float2bfloat16(v.z), h3 = __float2bfloat16(v.w);
    bf l0 = __float2bfloat16(v.x - __bfloat162float(h0));
    bf l1 = __float2bfloat16(v.y - __bfloat162float(h1));
    bf l2 = __float2bfloat16(v.z - __bfloat162float(h2));
    bf l3 = __float2bfloat16(v.w - __bfloat162float(h3));
    uint2 hp, lp;
    hp.x = (uint32_t)__bfloat16_as_ushort(h0) | ((uint32_t)__bfloat16_as_ushort(h1) << 16);
    hp.y = (uint32_t)__bfloat16_as_ushort(h2) | ((uint32_t)__bfloat16_as_ushort(h3) << 16);
    lp.x = (uint32_t)__bfloat16_as_ushort(l0) | ((uint32_t)__bfloat16_as_ushort(l1) << 16);
    lp.y = (uint32_t)__bfloat16_as_ushort(l2) | ((uint32_t)__bfloat16_as_ushort(l3) << 16);
    *(uint2*)(hi + i) = hp;
    *(uint2*)(lo + i) = lp;
}

// ===================== split-bf16 warp-MMA GEMM ============================
// C[M,N] = act(Ahi/lo[M,K] @ (Bhi/lo[N,K])^T + bias)
// BM=BN=128, BK=64. 8 warps (4 m x 2 n), warp tile 32x64.
// Smem: per stage 4 tiers (Ahi,Alo,Bhi,Blo), each 128 rows x 144B (64 bf16
// data + 16B pad -> conflict-free ldmatrix). 2-stage cp.async double buffer.
#define ROW_BYTES   144u
#define TIER_BYTES  18432u           // 128 * 144
#define STAGE_BYTES 73728u           // 4 * TIER_BYTES
#define GSMEM_SZ    (2 * 73728 + 512)

template <int ACT, bool MINMAX, bool HASBIAS, bool SPLITOUT>
__global__ void __launch_bounds__(256, 1)
gemm_mma(const bf* __restrict__ Ahi, const bf* __restrict__ Alo,
         const bf* __restrict__ Bhi, const bf* __restrict__ Blo,
         const float* __restrict__ bias,
         float* __restrict__ Cf, bf* __restrict__ Chi, bf* __restrict__ Clo,
         int M, int N, int K)
{
    extern __shared__ char smem[];
    const uint32_t sb = smem_to_u32(smem);
    const int tid = threadIdx.x;
    const int wid = tid >> 5, lane = tid & 31;
    const int wm = wid & 3, wn = wid >> 2;
    const int bm = blockIdx.y * 128, bn = blockIdx.x * 128;

    float* biasS = (float*)(smem + 2 * STAGE_BYTES);
    if (HASBIAS && tid < 128) biasS[tid] = bias[bn + tid];

    // ldmatrix per-lane row-address offsets (within a tier)
    const int quad = lane >> 3, r8 = lane & 7;
    const uint32_t aoff = (uint32_t)((wm * 32 + (quad & 1) * 8 + r8) * ROW_BYTES
                                     + (quad >> 1) * 16);
    const uint32_t boff = (uint32_t)((wn * 64 + (quad >> 1) * 8 + r8) * ROW_BYTES
                                     + (quad & 1) * 16);

    float acc[2][8][4];
#pragma unroll
    for (int i = 0; i < 2; i++)
#pragma unroll
        for (int j = 0; j < 8; j++)
#pragma unroll
            for (int q = 0; q < 4; q++) acc[i][j][q] = 0.0f;

    const int T = K >> 6;

    auto load_stage = [&](int st, int k0) {
        const uint32_t base = sb + (uint32_t)st * STAGE_BYTES;
#pragma unroll
        for (int i = 0; i < 16; i++) {
            int id = tid + i * 256;
            int tier = id >> 10;
            int rid = id & 1023;
            int row = rid >> 3, c = rid & 7;
            const bf* src;
            int rbase;
            if      (tier == 0) { src = Ahi; rbase = bm; }
            else if (tier == 1) { src = Alo; rbase = bm; }
            else if (tier == 2) { src = Bhi; rbase = bn; }
            else                { src = Blo; rbase = bn; }
            const bf* g = src + (size_t)(rbase + row) * K + k0 + c * 8;
            uint32_t d = base + (uint32_t)tier * TIER_BYTES
                         + (uint32_t)row * ROW_BYTES + (uint32_t)c * 16;
            CP_ASYNC16(d, g);
        }
        CP_COMMIT();
    };

    auto compute_stage = [&](int st) {
        const uint32_t base = sb + (uint32_t)st * STAGE_BYTES;
        const uint32_t Ah = base, Al = base + TIER_BYTES;
        const uint32_t Bh = base + 2 * TIER_BYTES, Bl = base + 3 * TIER_BYTES;
#pragma unroll
        for (int ks = 0; ks < 4; ks++) {
            const uint32_t ko = (uint32_t)ks * 32;
            uint32_t ah[2][4], al[2][4];
            LDSM_X4(ah[0][0], ah[0][1], ah[0][2], ah[0][3], Ah + aoff + ko);
            LDSM_X4(ah[1][0], ah[1][1], ah[1][2], ah[1][3], Ah + aoff + 2304 + ko);
            LDSM_X4(al[0][0], al[0][1], al[0][2], al[0][3], Al + aoff + ko);
            LDSM_X4(al[1][0], al[1][1], al[1][2], al[1][3], Al + aoff + 2304 + ko);
#pragma unroll
            for (int half = 0; half < 2; half++) {
                uint32_t bh[2][4], bl[2][4];
#pragma unroll
                for (int p = 0; p < 2; p++) {
                    uint32_t po = (uint32_t)(half * 2 + p) * 2304 + ko;
                    LDSM_X4(bh[p][0], bh[p][1], bh[p][2], bh[p][3], Bh + boff + po);
                    LDSM_X4(bl[p][0], bl[p][1], bl[p][2], bl[p][3], Bl + boff + po);
                }
#pragma unroll
                for (int p = 0; p < 2; p++)
#pragma unroll
                    for (int sub = 0; sub < 2; sub++) {
                        int ni = half * 4 + p * 2 + sub;
                        uint32_t h0 = bh[p][sub * 2], h1 = bh[p][sub * 2 + 1];
                        uint32_t l0 = bl[p][sub * 2], l1 = bl[p][sub * 2 + 1];
#pragma unroll
                        for (int mi = 0; mi < 2; mi++) {
                            mma_bf16(acc[mi][ni], ah[mi][0], ah[mi][1], ah[mi][2], ah[mi][3], h0, h1);
                            mma_bf16(acc[mi][ni], ah[mi][0], ah[mi][1], ah[mi][2], ah[mi][3], l0, l1);
                            mma_bf16(acc[mi][ni], al[mi][0], al[mi][1], al[mi][2], al[mi][3], h0, h1);
                        }
                    }
            }
        }
    };

    load_stage(0, 0);
    for (int t = 0; t < T; t++) {
        if (t + 1 < T) { load_stage((t + 1) & 1, (t + 1) * 64); CP_WAIT1(); }
        else          { CP_WAIT0(); }
        __syncthreads();
        compute_stage(t & 1);
        __syncthreads();
    }

    // ---------------- epilogue ----------------
    float lmin = INFINITY, lmax = -INFINITY;
    const int rbase = bm + wm * 32 + (lane >> 2);
    const int cloc0 = wn * 64 + (lane & 3) * 2;
#pragma unroll
    for (int mi = 0; mi < 2; mi++) {
#pragma unroll
        for (int ni = 0; ni < 8; ni++) {
            int cl = cloc0 + ni * 8;
            int n0 = bn + cl;
            float b0 = 0.f, b1 = 0.f;
            if (HASBIAS) { b0 = biasS[cl]; b1 = biasS[cl + 1]; }
#pragma unroll
            for (int h = 0; h < 2; h++) {
                int m = rbase + mi * 16 + h * 8;
                float v0 = apply_act(acc[mi][ni][h * 2 + 0] + b0, ACT);
                float v1 = apply_act(acc[mi][ni][h * 2 + 1] + b1, ACT);
                if (SPLITOUT) {
                    bf h0 = __float2bfloat16(v0), h1 = __float2bfloat16(v1);
                    bf q0 = __float2bfloat16(v0 - __bfloat162float(h0));
                    bf q1 = __float2bfloat16(v1 - __bfloat162float(h1));
                    uint32_t hw = (uint32_t)__bfloat16_as_ushort(h0) |
                                  ((uint32_t)__bfloat16_as_ushort(h1) << 16);
                    uint32_t lw = (uint32_t)__bfloat16_as_ushort(q0) |
                                  ((uint32_t)__bfloat16_as_ushort(q1) << 16);
                    *(uint32_t*)(Chi + (size_t)m * N + n0) = hw;
                    *(uint32_t*)(Clo + (size_t)m * N + n0) = lw;
                } else {
                    if (MINMAX) {
                        lmin = fminf(lmin, fminf(v0, v1));
                        lmax = fmaxf(lmax, fmaxf(v0, v1));
                    }
                    *(float2*)(Cf + (size_t)m * N + n0) = make_float2(v0, v1);
                }
            }
        }
    }

    if (MINMAX) {
        float* red = (float*)smem;   // stage memory is free now
        __syncthreads();
        red[tid] = lmin; red[256 + tid] = lmax;
        __syncthreads();
        if (tid < 128) {
            red[tid] = fminf(red[tid], red[tid + 128]);
            red[256 + tid] = fmaxf(red[256 + tid], red[256 + tid + 128]);
        }
        __syncthreads();
        if (tid < 64) {
            red[tid] = fminf(red[tid], red[tid + 64]);
            red[256 + tid] = fmaxf(red[256 + tid], red[256 + tid + 64]);
        }
        __syncthreads();
        if (tid < 32) {
            float a = fminf(red[tid], red[tid + 32]);
            float b = fmaxf(red[256 + tid], red[256 + tid + 32]);
#pragma unroll
            for (int o = 16; o > 0; o >>= 1) {
                a = fminf(a, __shfl_down_sync(0xffffffffu, a, o));
                b = fmaxf(b, __shfl_down_sync(0xffffffffu, b, o));
            }
            if (tid == 0) {
                atomicMin(&g_minkey, f2key(a));
                atomicMax(&g_maxkey, f2key(b));
            }
        }
    }
}

// ===================== N=1 projection from hi/lo bf16 ======================
template <int ACT>
__global__ void __launch_bounds__(256)
rowdot_bf(const bf* __restrict__ hi, const bf* __restrict__ lo,
          const float* __restrict__ w, const float* __restrict__ bias,
          float* __restrict__ out, int K)
{
    const int warp = threadIdx.x >> 5, lane = threadIdx.x & 31;
    const int row = blockIdx.x * 8 + warp;
    const bf* h = hi + (size_t)row * K;
    const bf* l = lo + (size_t)row * K;
    float s = 0.0f;
    for (int k = lane * 8; k < K; k += 32 * 8) {
        uint4 hv = *(const uint4*)(h + k);
        uint4 lv = *(const uint4*)(l + k);
        float4 w0 = *(const float4*)(w + k);
        float4 w1 = *(const float4*)(w + k + 4);
        const uint32_t hu[4] = {hv.x, hv.y, hv.z, hv.w};
        const uint32_t lu[4] = {lv.x, lv.y, lv.z, lv.w};
        const float wf[8] = {w0.x, w0.y, w0.z, w0.w, w1.x, w1.y, w1.z, w1.w};
#pragma unroll
        for (int q = 0; q < 4; q++) {
            __nv_bfloat162 h2 = *(const __nv_bfloat162*)&hu[q];
            __nv_bfloat162 l2 = *(const __nv_bfloat162*)&lu[q];
            s += (__low2float(h2) + __low2float(l2)) * wf[q * 2];
            s += (__high2float(h2) + __high2float(l2)) * wf[q * 2 + 1];
        }
    }
#pragma unroll
    for (int o = 16; o > 0; o >>= 1) s += __shfl_down_sync(0xffffffffu, s, o);
    if (lane == 0) out[row] = apply_act(s + bias[0], ACT);
}

// ===================== min/max init + final rescale ========================
__global__ void init_minmax_k() { g_minkey = 0xFFFFFFFFu; g_maxkey = 0u; }

__global__ void __launch_bounds__(256)
scale_out(const float* __restrict__ s, float* __restrict__ out)
{
    float mn = key2f(g_minkey);
    float mx = key2f(g_maxkey);
    float inv = 1.0f / (mx - mn);
    size_t i = ((size_t)blockIdx.x * blockDim.x + threadIdx.x) * 4;
    float4 v = *(const float4*)&s[i];
    float4 o;
    o.x = (v.x - mn) * inv; o.y = (v.y - mn) * inv;
    o.z = (v.z - mn) * inv; o.w = (v.w - mn) * inv;
    *(float4*)&out[i] = o;
}

// ===================== host launch =========================================
static void launch_gemm_act(int act, const bf* Ahi, const bf* Alo,
                            const bf* Bhi, const bf* Blo, const float* bias,
                            bf* Chi, bf* Clo, int M, int N, int K)
{
    dim3 grid(N / 128, M / 128), blk(256);
    if (act == ACT_RELU) {
        cudaFuncSetAttribute(gemm_mma<ACT_RELU, false, true, true>,
                             cudaFuncAttributeMaxDynamicSharedMemorySize, GSMEM_SZ);
        gemm_mma<ACT_RELU, false, true, true><<<grid, blk, GSMEM_SZ>>>(
            Ahi, Alo, Bhi, Blo, bias, nullptr, Chi, Clo, M, N, K);
    } else {
        cudaFuncSetAttribute(gemm_mma<ACT_SIG, false, true, true>,
                             cudaFuncAttributeMaxDynamicSharedMemorySize, GSMEM_SZ);
        gemm_mma<ACT_SIG, false, true, true><<<grid, blk, GSMEM_SZ>>>(
            Ahi, Alo, Bhi, Blo, bias, nullptr, Chi, Clo, M, N, K);
    }
}

extern "C" void kernel_launch(void* const* d_in, const int* in_sizes, int n_in,
                              void* d_out, int out_size)
{
    (void)in_sizes; (void)n_in; (void)out_size;
    const float* x1   = (const float*)d_in[0];
    const float* x2   = (const float*)d_in[1];
    const float* W1_1 = (const float*)d_in[2];   const float* b1_1 = (const float*)d_in[3];
    const float* W1_2 = (const float*)d_in[4];   const float* b1_2 = (const float*)d_in[5];
    const float* W1_3 = (const float*)d_in[6];   const float* b1_3 = (const float*)d_in[7];
    const float* W1_4 = (const float*)d_in[8];   const float* b1_4 = (const float*)d_in[9];
    const float* W1_5 = (const float*)d_in[10];  const float* b1_5 = (const float*)d_in[11];
    const float* Wp1  = (const float*)d_in[12];  const float* bp1  = (const float*)d_in[13];
    const float* W2_1 = (const float*)d_in[14];  const float* b2_1 = (const float*)d_in[15];
    const float* W2_2 = (const float*)d_in[16];  const float* b2_2 = (const float*)d_in[17];
    const float* W2_3 = (const float*)d_in[18];  const float* b2_3 = (const float*)d_in[19];
    const float* Wp2  = (const float*)d_in[20];  const float* bp2  = (const float*)d_in[21];

    float* out = (float*)d_out;
    const int B = 4096;
    const size_t NSC = (size_t)4096 * 4096;

    bf *ahi, *alo, *bhi, *blo, *x1h, *x1l, *x2h, *x2l, *whi, *wlo, *inh, *inl;
    float* scores;
    cudaGetSymbolAddress((void**)&ahi, g_ahi);    cudaGetSymbolAddress((void**)&alo, g_alo);
    cudaGetSymbolAddress((void**)&bhi, g_bhi);    cudaGetSymbolAddress((void**)&blo, g_blo);
    cudaGetSymbolAddress((void**)&x1h, g_x1v_hi); cudaGetSymbolAddress((void**)&x1l, g_x1v_lo);
    cudaGetSymbolAddress((void**)&x2h, g_x2v_hi); cudaGetSymbolAddress((void**)&x2l, g_x2v_lo);
    cudaGetSymbolAddress((void**)&whi, g_whi);    cudaGetSymbolAddress((void**)&wlo, g_wlo);
    cudaGetSymbolAddress((void**)&inh, g_inhi);   cudaGetSymbolAddress((void**)&inl, g_inlo);
    cudaGetSymbolAddress((void**)&scores, g_scores);

    init_minmax_k<<<1, 1>>>();

    // split inputs + weights into bf16 hi/lo
    struct { const float* p; unsigned off; int n; bool isw; } cv[10] = {
        {x1, OX1, 4194304, false}, {x2, OX2, 2097152, false},
        {W1_1, OW11, 2097152, true}, {W1_2, OW12, 2097152, true},
        {W1_3, OW13, 524288, true},  {W1_4, OW14, 524288, true},
        {W1_5, OW15, 2097152, true}, {W2_1, OW21, 524288, true},
        {W2_2, OW22, 524288, true},  {W2_3, OW23, 524288, true},
    };
    for (int i = 0; i < 10; i++) {
        bf* h = (cv[i].isw ? whi : inh) + cv[i].off;
        bf* l = (cv[i].isw ? wlo : inl) + cv[i].off;
        split_f32<<<cv[i].n / 1024, 256>>>(cv[i].p, h, l, cv[i].n);
    }

    // branch 1
    launch_gemm_act(ACT_RELU, inh + OX1, inl + OX1, whi + OW11, wlo + OW11, b1_1, ahi, alo, B, 2048, 1024);
    launch_gemm_act(ACT_RELU, ahi, alo, whi + OW12, wlo + OW12, b1_2, bhi, blo, B, 1024, 2048);
    launch_gemm_act(ACT_SIG,  bhi, blo, whi + OW13, wlo + OW13, b1_3, x1h, x1l, B, 512, 1024);
    launch_gemm_act(ACT_RELU, x1h, x1l, whi + OW14, wlo + OW14, b1_4, ahi, alo, B, 1024, 512);
    launch_gemm_act(ACT_RELU, ahi, alo, whi + OW15, wlo + OW15, b1_5, bhi, blo, B, 2048, 1024);
    rowdot_bf<ACT_SIG><<<B / 8, 256>>>(bhi, blo, Wp1, bp1, out + 0, 2048);            // pre_data

    // branch 2
    launch_gemm_act(ACT_RELU, inh + OX2, inl + OX2, whi + OW21, wlo + OW21, b2_1, ahi, alo, B, 1024, 512);
    launch_gemm_act(ACT_SIG,  ahi, alo, whi + OW22, wlo + OW22, b2_2, x2h, x2l, B, 512, 1024);
    launch_gemm_act(ACT_RELU, x2h, x2l, whi + OW23, wlo + OW23, b2_3, ahi, alo, B, 1024, 512);
    rowdot_bf<ACT_SIG><<<B / 8, 256>>>(ahi, alo, Wp2, bp2, out + 4096 + NSC, 1024);   // pre_model

    // cross scores with fused global min/max
    {
        dim3 grid(4096 / 128, B / 128), blk(256);
        cudaFuncSetAttribute(gemm_mma<ACT_NONE, true, false, false>,
                             cudaFuncAttributeMaxDynamicSharedMemorySize, GSMEM_SZ);
        gemm_mma<ACT_NONE, true, false, false><<<grid, blk, GSMEM_SZ>>>(
            x1h, x1l, x2h, x2l, nullptr, scores, nullptr, nullptr, B, 4096, 512);
    }

    // min-max rescale -> pre_dm
    scale_out<<<(unsigned)(NSC / 4 / 256), 256>>>(scores, out + 4096);
}

// round 4
// speedup vs baseline: 2.3730x; 1.0175x over previous
#include <cuda_runtime.h>
#include <cuda_bf16.h>
#include <math.h>
#include <stdint.h>

typedef __nv_bfloat16 bf;

// ===================== device scratch (no allocation allowed) ==============
__device__ bf g_ahi[4096 * 2048];
__device__ bf g_alo[4096 * 2048];
__device__ bf g_bhi[4096 * 2048];
__device__ bf g_blo[4096 * 2048];
__device__ bf g_x1v_hi[4096 * 512];
__device__ bf g_x1v_lo[4096 * 512];
__device__ bf g_x2v_hi[4096 * 512];
__device__ bf g_x2v_lo[4096 * 512];
__device__ bf g_whi[8912896];
__device__ bf g_wlo[8912896];
__device__ bf g_inhi[6291456];
__device__ bf g_inlo[6291456];
__device__ float g_scores[(size_t)4096 * 4096];
__device__ unsigned g_minkey;
__device__ unsigned g_maxkey;

// weight pool offsets (elements)
#define OW11 0u
#define OW12 2097152u
#define OW13 4194304u
#define OW14 4718592u
#define OW15 5242880u
#define OW21 7340032u
#define OW22 7864320u
#define OW23 8388608u
#define OX1  0u
#define OX2  4194304u

// ===================== PTX helpers (sm_80-era, compiles for sm_103) ========
__device__ __forceinline__ uint32_t smem_to_u32(const void* p) {
    uint32_t a;
    asm("{ .reg .u64 t; cvta.to.shared.u64 t, %1; cvt.u32.u64 %0, t; }"
        : "=r"(a) : "l"(p));
    return a;
}

#define CP_ASYNC16(dst, src) \
    asm volatile("cp.async.cg.shared.global [%0], [%1], 16;" \
                 :: "r"(dst), "l"(src) : "memory")
#define CP_COMMIT() asm volatile("cp.async.commit_group;" ::: "memory")
#define CP_WAIT1()  asm volatile("cp.async.wait_group 1;" ::: "memory")
#define CP_WAIT0()  asm volatile("cp.async.wait_group 0;" ::: "memory")

#define LDSM_X4(r0, r1, r2, r3, addr) \
    asm volatile("ldmatrix.sync.aligned.m8n8.x4.shared.b16 {%0,%1,%2,%3}, [%4];" \
                 : "=r"(r0), "=r"(r1), "=r"(r2), "=r"(r3) : "r"(addr))

__device__ __forceinline__ void mma_bf16(float* c, uint32_t a0, uint32_t a1,
                                         uint32_t a2, uint32_t a3,
                                         uint32_t b0, uint32_t b1) {
    asm volatile(
        "mma.sync.aligned.m16n8k16.row.col.f32.bf16.bf16.f32 "
        "{%0,%1,%2,%3}, {%4,%5,%6,%7}, {%8,%9}, {%0,%1,%2,%3};"
        : "+f"(c[0]), "+f"(c[1]), "+f"(c[2]), "+f"(c[3])
        : "r"(a0), "r"(a1), "r"(a2), "r"(a3), "r"(b0), "r"(b1));
}

// ===================== misc helpers ========================================
__device__ __forceinline__ unsigned f2key(float f) {
    unsigned u = __float_as_uint(f);
    return (u & 0x80000000u) ? ~u : (u | 0x80000000u);
}
__device__ __forceinline__ float key2f(unsigned k) {
    unsigned u = (k & 0x80000000u) ? (k ^ 0x80000000u) : ~k;
    return __uint_as_float(u);
}
enum { ACT_NONE = 0, ACT_RELU = 1, ACT_SIG = 2 };
__device__ __forceinline__ float apply_act(float v, int act) {
    if (act == ACT_RELU) return fmaxf(v, 0.0f);
    if (act == ACT_SIG)  return 1.0f / (1.0f + expf(-v));
    return v;
}

// ===================== fp32 -> bf16 hi/lo split ============================
__global__ void __launch_bounds__(256)
split_f32(const float* __restrict__ in, bf* __restrict__ hi,
          bf* __restrict__ lo, int n)
{
    int i = (blockIdx.x * 256 + threadIdx.x) * 4;
    if (i >= n) return;
    float4 v = *(const float4*)(in + i);
    bf h0 = __float2bfloat16(v.x), h1 = __float2bfloat16(v.y);
    bf h2 = __float2bfloat16(v.z), h3 = __float2bfloat16(v.w);
    bf l0 = __float2bfloat16(v.x - __bfloat162float(h0));
    bf l1 = __float2bfloat16(v.y - __bfloat162float(h1));
    bf l2 = __float2bfloat16(v.z - __bfloat162float(h2));
    bf l3 = __float2bfloat16(v.w - __bfloat162float(h3));
    uint2 hp, lp;
    hp.x = (uint32_t)__bfloat16_as_ushort(h0) | ((uint32_t)__bfloat16_as_ushort(h1) << 16);
    hp.y = (uint32_t)__bfloat16_as_ushort(h2) | ((uint32_t)__bfloat16_as_ushort(h3) << 16);
    lp.x = (uint32_t)__bfloat16_as_ushort(l0) | ((uint32_t)__bfloat16_as_ushort(l1) << 16);
    lp.y = (uint32_t)__bfloat16_as_ushort(l2) | ((uint32_t)__bfloat16_as_ushort(l3) << 16);
    *(uint2*)(hi + i) = hp;
    *(uint2*)(lo + i) = lp;
}

// ===================== split-bf16 warp-MMA GEMM ============================
// C[M,N] = act(Ahi/lo[M,K] @ (Bhi/lo[N,K])^T + bias)
// BM=BN=128, BK=64. 16 warps (4 m x 4 n), warp tile 32x32.
// Smem: per stage 4 tiers (Ahi,Alo,Bhi,Blo), each 128 rows x 144B.
// 3-stage cp.async pipeline, one __syncthreads per stage.
#define ROW_BYTES   144u
#define TIER_BYTES  18432u           // 128 * 144
#define STAGE_BYTES 73728u           // 4 * TIER_BYTES
#define NSTAGE      3
#define GSMEM_SZ    (NSTAGE * 73728 + 1024)

template <int ACT, bool MINMAX, bool HASBIAS, bool SPLITOUT>
__global__ void __launch_bounds__(512, 1)
gemm_mma(const bf* __restrict__ Ahi, const bf* __restrict__ Alo,
         const bf* __restrict__ Bhi, const bf* __restrict__ Blo,
         const float* __restrict__ bias,
         float* __restrict__ Cf, bf* __restrict__ Chi, bf* __restrict__ Clo,
         int M, int N, int K)
{
    extern __shared__ char smem[];
    const uint32_t sb = smem_to_u32(smem);
    const int tid = threadIdx.x;
    const int wid = tid >> 5, lane = tid & 31;
    const int wm = wid & 3, wn = wid >> 2;        // 4 x 4 warps
    const int bm = blockIdx.y * 128, bn = blockIdx.x * 128;

    float* biasS = (float*)(smem + NSTAGE * STAGE_BYTES);
    if (HASBIAS && tid < 128) biasS[tid] = bias[bn + tid];

    // ldmatrix per-lane row-address offsets (within a tier)
    const int quad = lane >> 3, r8 = lane & 7;
    const uint32_t aoff = (uint32_t)((wm * 32 + (quad & 1) * 8 + r8) * ROW_BYTES
                                     + (quad >> 1) * 16);
    const uint32_t boff = (uint32_t)((wn * 32 + (quad >> 1) * 8 + r8) * ROW_BYTES
                                     + (quad & 1) * 16);

    float acc[2][4][4];
#pragma unroll
    for (int i = 0; i < 2; i++)
#pragma unroll
        for (int j = 0; j < 4; j++)
#pragma unroll
            for (int q = 0; q < 4; q++) acc[i][j][q] = 0.0f;

    const int T = K >> 6;

    auto load_stage = [&](int st, int k0) {
        const uint32_t base = sb + (uint32_t)st * STAGE_BYTES;
#pragma unroll
        for (int i = 0; i < 8; i++) {
            int id = tid + i * 512;              // 0..4095
            int tier = id >> 10;
            int rid = id & 1023;
            int row = rid >> 3, c = rid & 7;
            const bf* src;
            int rbase;
            if      (tier == 0) { src = Ahi; rbase = bm; }
            else if (tier == 1) { src = Alo; rbase = bm; }
            else if (tier == 2) { src = Bhi; rbase = bn; }
            else                { src = Blo; rbase = bn; }
            const bf* g = src + (size_t)(rbase + row) * K + k0 + c * 8;
            uint32_t d = base + (uint32_t)tier * TIER_BYTES
                         + (uint32_t)row * ROW_BYTES + (uint32_t)c * 16;
            CP_ASYNC16(d, g);
        }
        CP_COMMIT();
    };

    auto compute_stage = [&](int st) {
        const uint32_t base = sb + (uint32_t)st * STAGE_BYTES;
        const uint32_t Ah = base, Al = base + TIER_BYTES;
        const uint32_t Bh = base + 2 * TIER_BYTES, Bl = base + 3 * TIER_BYTES;
#pragma unroll
        for (int ks = 0; ks < 4; ks++) {
            const uint32_t ko = (uint32_t)ks * 32;
            uint32_t ah[2][4], al[2][4], bh[2][4], bl[2][4];
            LDSM_X4(ah[0][0], ah[0][1], ah[0][2], ah[0][3], Ah + aoff + ko);
            LDSM_X4(ah[1][0], ah[1][1], ah[1][2], ah[1][3], Ah + aoff + 2304 + ko);
            LDSM_X4(al[0][0], al[0][1], al[0][2], al[0][3], Al + aoff + ko);
            LDSM_X4(al[1][0], al[1][1], al[1][2], al[1][3], Al + aoff + 2304 + ko);
            LDSM_X4(bh[0][0], bh[0][1], bh[0][2], bh[0][3], Bh + boff + ko);
            LDSM_X4(bh[1][0], bh[1][1], bh[1][2], bh[1][3], Bh + boff + 2304 + ko);
            LDSM_X4(bl[0][0], bl[0][1], bl[0][2], bl[0][3], Bl + boff + ko);
            LDSM_X4(bl[1][0], bl[1][1], bl[1][2], bl[1][3], Bl + boff + 2304 + ko);
#pragma unroll
            for (int p = 0; p < 2; p++)
#pragma unroll
                for (int sub = 0; sub < 2; sub++) {
                    int nj = p * 2 + sub;
                    uint32_t h0 = bh[p][sub * 2], h1 = bh[p][sub * 2 + 1];
                    uint32_t l0 = bl[p][sub * 2], l1 = bl[p][sub * 2 + 1];
#pragma unroll
                    for (int mi = 0; mi < 2; mi++) {
                        mma_bf16(acc[mi][nj], ah[mi][0], ah[mi][1], ah[mi][2], ah[mi][3], h0, h1);
                        mma_bf16(acc[mi][nj], ah[mi][0], ah[mi][1], ah[mi][2], ah[mi][3], l0, l1);
                        mma_bf16(acc[mi][nj], al[mi][0], al[mi][1], al[mi][2], al[mi][3], h0, h1);
                    }
                }
        }
    };

    // prologue: 2 stages in flight
    load_stage(0, 0);
    load_stage(1, 64);
    for (int t = 0; t < T; t++) {
        if (t + 1 < T) CP_WAIT1(); else CP_WAIT0();
        __syncthreads();
        if (t + 2 < T) load_stage((t + 2) % NSTAGE, (t + 2) * 64);
        compute_stage(t % NSTAGE);
    }

    // ---------------- epilogue ----------------
    float lmin = INFINITY, lmax = -INFINITY;
    const int rbase = bm + wm * 32 + (lane >> 2);
    const int cloc0 = wn * 32 + (lane & 3) * 2;
#pragma unroll
    for (int mi = 0; mi < 2; mi++) {
#pragma unroll
        for (int nj = 0; nj < 4; nj++) {
            int cl = cloc0 + nj * 8;
            int n0 = bn + cl;
            float b0 = 0.f, b1 = 0.f;
            if (HASBIAS) { b0 = biasS[cl]; b1 = biasS[cl + 1]; }
#pragma unroll
            for (int h = 0; h < 2; h++) {
                int m = rbase + mi * 16 + h * 8;
                float v0 = apply_act(acc[mi][nj][h * 2 + 0] + b0, ACT);
                float v1 = apply_act(acc[mi][nj][h * 2 + 1] + b1, ACT);
                if (SPLITOUT) {
                    bf h0 = __float2bfloat16(v0), h1 = __float2bfloat16(v1);
                    bf q0 = __float2bfloat16(v0 - __bfloat162float(h0));
                    bf q1 = __float2bfloat16(v1 - __bfloat162float(h1));
                    uint32_t hw = (uint32_t)__bfloat16_as_ushort(h0) |
                                  ((uint32_t)__bfloat16_as_ushort(h1) << 16);
                    uint32_t lw = (uint32_t)__bfloat16_as_ushort(q0) |
                                  ((uint32_t)__bfloat16_as_ushort(q1) << 16);
                    *(uint32_t*)(Chi + (size_t)m * N + n0) = hw;
                    *(uint32_t*)(Clo + (size_t)m * N + n0) = lw;
                } else {
                    if (MINMAX) {
                        lmin = fminf(lmin, fminf(v0, v1));
                        lmax = fmaxf(lmax, fmaxf(v0, v1));
                    }
                    *(float2*)(Cf + (size_t)m * N + n0) = make_float2(v0, v1);
                }
            }
        }
    }

    if (MINMAX) {
        float* red = (float*)smem;   // stage memory is free now
        __syncthreads();
        red[tid] = lmin; red[512 + tid] = lmax;
        __syncthreads();
#pragma unroll
        for (int s = 256; s >= 64; s >>= 1) {
            if (tid < s) {
                red[tid] = fminf(red[tid], red[tid + s]);
                red[512 + tid] = fmaxf(red[512 + tid], red[512 + tid + s]);
            }
            __syncthreads();
        }
        if (tid < 32) {
            float a = fminf(red[tid], red[tid + 32]);
            float b = fmaxf(red[512 + tid], red[512 + tid + 32]);
#pragma unroll
            for (int o = 16; o > 0; o >>= 1) {
                a = fminf(a, __shfl_down_sync(0xffffffffu, a, o));
                b = fmaxf(b, __shfl_down_sync(0xffffffffu, b, o));
            }
            if (tid == 0) {
                atomicMin(&g_minkey, f2key(a));
                atomicMax(&g_maxkey, f2key(b));
            }
        }
    }
}

// ===================== N=1 projection from hi/lo bf16 ======================
template <int ACT>
__global__ void __launch_bounds__(256)
rowdot_bf(const bf* __restrict__ hi, const bf* __restrict__ lo,
          const float* __restrict__ w, const float* __restrict__ bias,
          float* __restrict__ out, int K)
{
    const int warp = threadIdx.x >> 5, lane = threadIdx.x & 31;
    const int row = blockIdx.x * 8 + warp;
    const bf* h = hi + (size_t)row * K;
    const bf* l = lo + (size_t)row * K;
    float s = 0.0f;
    for (int k = lane * 8; k < K; k += 32 * 8) {
        uint4 hv = *(const uint4*)(h + k);
        uint4 lv = *(const uint4*)(l + k);
        float4 w0 = *(const float4*)(w + k);
        float4 w1 = *(const float4*)(w + k + 4);
        const uint32_t hu[4] = {hv.x, hv.y, hv.z, hv.w};
        const uint32_t lu[4] = {lv.x, lv.y, lv.z, lv.w};
        const float wf[8] = {w0.x, w0.y, w0.z, w0.w, w1.x, w1.y, w1.z, w1.w};
#pragma unroll
        for (int q = 0; q < 4; q++) {
            __nv_bfloat162 h2 = *(const __nv_bfloat162*)&hu[q];
            __nv_bfloat162 l2 = *(const __nv_bfloat162*)&lu[q];
            s += (__low2float(h2) + __low2float(l2)) * wf[q * 2];
            s += (__high2float(h2) + __high2float(l2)) * wf[q * 2 + 1];
        }
    }
#pragma unroll
    for (int o = 16; o > 0; o >>= 1) s += __shfl_down_sync(0xffffffffu, s, o);
    if (lane == 0) out[row] = apply_act(s + bias[0], ACT);
}

// ===================== min/max init + final rescale ========================
__global__ void init_minmax_k() { g_minkey = 0xFFFFFFFFu; g_maxkey = 0u; }

__global__ void __launch_bounds__(256)
scale_out(const float* __restrict__ s, float* __restrict__ out)
{
    float mn = key2f(g_minkey);
    float mx = key2f(g_maxkey);
    float inv = 1.0f / (mx - mn);
    size_t i = ((size_t)blockIdx.x * blockDim.x + threadIdx.x) * 4;
    float4 v = *(const float4*)&s[i];
    float4 o;
    o.x = (v.x - mn) * inv; o.y = (v.y - mn) * inv;
    o.z = (v.z - mn) * inv; o.w = (v.w - mn) * inv;
    *(float4*)&out[i] = o;
}

// ===================== host launch =========================================
static void launch_gemm_act(int act, const bf* Ahi, const bf* Alo,
                            const bf* Bhi, const bf* Blo, const float* bias,
                            bf* Chi, bf* Clo, int M, int N, int K)
{
    dim3 grid(N / 128, M / 128), blk(512);
    if (act == ACT_RELU) {
        cudaFuncSetAttribute(gemm_mma<ACT_RELU, false, true, true>,
                             cudaFuncAttributeMaxDynamicSharedMemorySize, GSMEM_SZ);
        gemm_mma<ACT_RELU, false, true, true><<<grid, blk, GSMEM_SZ>>>(
            Ahi, Alo, Bhi, Blo, bias, nullptr, Chi, Clo, M, N, K);
    } else {
        cudaFuncSetAttribute(gemm_mma<ACT_SIG, false, true, true>,
                             cudaFuncAttributeMaxDynamicSharedMemorySize, GSMEM_SZ);
        gemm_mma<ACT_SIG, false, true, true><<<grid, blk, GSMEM_SZ>>>(
            Ahi, Alo, Bhi, Blo, bias, nullptr, Chi, Clo, M, N, K);
    }
}

extern "C" void kernel_launch(void* const* d_in, const int* in_sizes, int n_in,
                              void* d_out, int out_size)
{
    (void)in_sizes; (void)n_in; (void)out_size;
    const float* x1   = (const float*)d_in[0];
    const float* x2   = (const float*)d_in[1];
    const float* W1_1 = (const float*)d_in[2];   const float* b1_1 = (const float*)d_in[3];
    const float* W1_2 = (const float*)d_in[4];   const float* b1_2 = (const float*)d_in[5];
    const float* W1_3 = (const float*)d_in[6];   const float* b1_3 = (const float*)d_in[7];
    const float* W1_4 = (const float*)d_in[8];   const float* b1_4 = (const float*)d_in[9];
    const float* W1_5 = (const float*)d_in[10];  const float* b1_5 = (const float*)d_in[11];
    const float* Wp1  = (const float*)d_in[12];  const float* bp1  = (const float*)d_in[13];
    const float* W2_1 = (const float*)d_in[14];  const float* b2_1 = (const float*)d_in[15];
    const float* W2_2 = (const float*)d_in[16];  const float* b2_2 = (const float*)d_in[17];
    const float* W2_3 = (const float*)d_in[18];  const float* b2_3 = (const float*)d_in[19];
    const float* Wp2  = (const float*)d_in[20];  const float* bp2  = (const float*)d_in[21];

    float* out = (float*)d_out;
    const int B = 4096;
    const size_t NSC = (size_t)4096 * 4096;

    bf *ahi, *alo, *bhi, *blo, *x1h, *x1l, *x2h, *x2l, *whi, *wlo, *inh, *inl;
    float* scores;
    cudaGetSymbolAddress((void**)&ahi, g_ahi);    cudaGetSymbolAddress((void**)&alo, g_alo);
    cudaGetSymbolAddress((void**)&bhi, g_bhi);    cudaGetSymbolAddress((void**)&blo, g_blo);
    cudaGetSymbolAddress((void**)&x1h, g_x1v_hi); cudaGetSymbolAddress((void**)&x1l, g_x1v_lo);
    cudaGetSymbolAddress((void**)&x2h, g_x2v_hi); cudaGetSymbolAddress((void**)&x2l, g_x2v_lo);
    cudaGetSymbolAddress((void**)&whi, g_whi);    cudaGetSymbolAddress((void**)&wlo, g_wlo);
    cudaGetSymbolAddress((void**)&inh, g_inhi);   cudaGetSymbolAddress((void**)&inl, g_inlo);
    cudaGetSymbolAddress((void**)&scores, g_scores);

    init_minmax_k<<<1, 1>>>();

    // split inputs + weights into bf16 hi/lo
    struct { const float* p; unsigned off; int n; bool isw; } cv[10] = {
        {x1, OX1, 4194304, false}, {x2, OX2, 2097152, false},
        {W1_1, OW11, 2097152, true}, {W1_2, OW12, 2097152, true},
        {W1_3, OW13, 524288, true},  {W1_4, OW14, 524288, true},
        {W1_5, OW15, 2097152, true}, {W2_1, OW21, 524288, true},
        {W2_2, OW22, 524288, true},  {W2_3, OW23, 524288, true},
    };
    for (int i = 0; i < 10; i++) {
        bf* h = (cv[i].isw ? whi : inh) + cv[i].off;
        bf* l = (cv[i].isw ? wlo : inl) + cv[i].off;
        split_f32<<<cv[i].n / 1024, 256>>>(cv[i].p, h, l, cv[i].n);
    }

    // branch 1
    launch_gemm_act(ACT_RELU, inh + OX1, inl + OX1, whi + OW11, wlo + OW11, b1_1, ahi, alo, B, 2048, 1024);
    launch_gemm_act(ACT_RELU, ahi, alo, whi + OW12, wlo + OW12, b1_2, bhi, blo, B, 1024, 2048);
    launch_gemm_act(ACT_SIG,  bhi, blo, whi + OW13, wlo + OW13, b1_3, x1h, x1l, B, 512, 1024);
    launch_gemm_act(ACT_RELU, x1h, x1l, whi + OW14, wlo + OW14, b1_4, ahi, alo, B, 1024, 512);
    launch_gemm_act(ACT_RELU, ahi, alo, whi + OW15, wlo + OW15, b1_5, bhi, blo, B, 2048, 1024);
    rowdot_bf<ACT_SIG><<<B / 8, 256>>>(bhi, blo, Wp1, bp1, out + 0, 2048);            // pre_data

    // branch 2
    launch_gemm_act(ACT_RELU, inh + OX2, inl + OX2, whi + OW21, wlo + OW21, b2_1, ahi, alo, B, 1024, 512);
    launch_gemm_act(ACT_SIG,  ahi, alo, whi + OW22, wlo + OW22, b2_2, x2h, x2l, B, 512, 1024);
    launch_gemm_act(ACT_RELU, x2h, x2l, whi + OW23, wlo + OW23, b2_3, ahi, alo, B, 1024, 512);
    rowdot_bf<ACT_SIG><<<B / 8, 256>>>(ahi, alo, Wp2, bp2, out + 4096 + NSC, 1024);   // pre_model

    // cross scores with fused global min/max
    {
        dim3 grid(4096 / 128, B / 128), blk(512);
        cudaFuncSetAttribute(gemm_mma<ACT_NONE, true, false, false>,
                             cudaFuncAttributeMaxDynamicSharedMemorySize, GSMEM_SZ);
        gemm_mma<ACT_NONE, true, false, false><<<grid, blk, GSMEM_SZ>>>(
            x1h, x1l, x2h, x2l, nullptr, scores, nullptr, nullptr, B, 4096, 512);
    }

    // min-max rescale -> pre_dm
    scale_out<<<(unsigned)(NSC / 4 / 256), 256>>>(scores, out + 4096);
}

// round 5
// speedup vs baseline: 2.3752x; 1.0009x over previous
#include <cuda_runtime.h>
#include <cuda_bf16.h>
#include <math.h>
#include <stdint.h>

typedef __nv_bfloat16 bf;

// ===================== device scratch (no allocation allowed) ==============
__device__ bf g_ahi[4096 * 2048];
__device__ bf g_alo[4096 * 2048];
__device__ bf g_bhi[4096 * 2048];
__device__ bf g_blo[4096 * 2048];
__device__ bf g_x1v_hi[4096 * 512];
__device__ bf g_x1v_lo[4096 * 512];
__device__ bf g_x2v_hi[4096 * 512];
__device__ bf g_x2v_lo[4096 * 512];
__device__ bf g_whi[8912896];
__device__ bf g_wlo[8912896];
__device__ bf g_inhi[6291456];
__device__ bf g_inlo[6291456];
__device__ float g_scores[(size_t)4096 * 4096];
__device__ unsigned g_minkey;
__device__ unsigned g_maxkey;

// weight pool offsets (elements)
#define OW11 0u
#define OW12 2097152u
#define OW13 4194304u
#define OW14 4718592u
#define OW15 5242880u
#define OW21 7340032u
#define OW22 7864320u
#define OW23 8388608u
#define OX1  0u
#define OX2  4194304u

// ===================== PTX helpers (sm_80-era, compiles for sm_103) ========
__device__ __forceinline__ uint32_t smem_to_u32(const void* p) {
    uint32_t a;
    asm("{ .reg .u64 t; cvta.to.shared.u64 t, %1; cvt.u32.u64 %0, t; }"
        : "=r"(a) : "l"(p));
    return a;
}

#define CP_ASYNC16(dst, src) \
    asm volatile("cp.async.cg.shared.global [%0], [%1], 16;" \
                 :: "r"(dst), "l"(src) : "memory")
#define CP_COMMIT() asm volatile("cp.async.commit_group;" ::: "memory")
#define CP_WAIT1()  asm volatile("cp.async.wait_group 1;" ::: "memory")
#define CP_WAIT0()  asm volatile("cp.async.wait_group 0;" ::: "memory")

#define LDSM_X4(r0, r1, r2, r3, addr) \
    asm volatile("ldmatrix.sync.aligned.m8n8.x4.shared.b16 {%0,%1,%2,%3}, [%4];" \
                 : "=r"(r0), "=r"(r1), "=r"(r2), "=r"(r3) : "r"(addr))

__device__ __forceinline__ void mma_bf16(float* c, uint32_t a0, uint32_t a1,
                                         uint32_t a2, uint32_t a3,
                                         uint32_t b0, uint32_t b1) {
    asm volatile(
        "mma.sync.aligned.m16n8k16.row.col.f32.bf16.bf16.f32 "
        "{%0,%1,%2,%3}, {%4,%5,%6,%7}, {%8,%9}, {%0,%1,%2,%3};"
        : "+f"(c[0]), "+f"(c[1]), "+f"(c[2]), "+f"(c[3])
        : "r"(a0), "r"(a1), "r"(a2), "r"(a3), "r"(b0), "r"(b1));
}

// ===================== misc helpers ========================================
__device__ __forceinline__ unsigned f2key(float f) {
    unsigned u = __float_as_uint(f);
    return (u & 0x80000000u) ? ~u : (u | 0x80000000u);
}
__device__ __forceinline__ float key2f(unsigned k) {
    unsigned u = (k & 0x80000000u) ? (k ^ 0x80000000u) : ~k;
    return __uint_as_float(u);
}
enum { ACT_NONE = 0, ACT_RELU = 1, ACT_SIG = 2 };
__device__ __forceinline__ float apply_act(float v, int act) {
    if (act == ACT_RELU) return fmaxf(v, 0.0f);
    if (act == ACT_SIG)  return 1.0f / (1.0f + expf(-v));
    return v;
}

// ===================== fp32 -> bf16 hi/lo split ============================
__global__ void __launch_bounds__(256)
split_f32(const float* __restrict__ in, bf* __restrict__ hi,
          bf* __restrict__ lo, int n)
{
    int i = (blockIdx.x * 256 + threadIdx.x) * 4;
    if (i >= n) return;
    float4 v = *(const float4*)(in + i);
    bf h0 = __float2bfloat16(v.x), h1 = __float2bfloat16(v.y);
    bf h2 = __float2bfloat16(v.z), h3 = __float2bfloat16(v.w);
    bf l0 = __float2bfloat16(v.x - __bfloat162float(h0));
    bf l1 = __float2bfloat16(v.y - __bfloat162float(h1));
    bf l2 = __float2bfloat16(v.z - __bfloat162float(h2));
    bf l3 = __float2bfloat16(v.w - __bfloat162float(h3));
    uint2 hp, lp;
    hp.x = (uint32_t)__bfloat16_as_ushort(h0) | ((uint32_t)__bfloat16_as_ushort(h1) << 16);
    hp.y = (uint32_t)__bfloat16_as_ushort(h2) | ((uint32_t)__bfloat16_as_ushort(h3) << 16);
    lp.x = (uint32_t)__bfloat16_as_ushort(l0) | ((uint32_t)__bfloat16_as_ushort(l1) << 16);
    lp.y = (uint32_t)__bfloat16_as_ushort(l2) | ((uint32_t)__bfloat16_as_ushort(l3) << 16);
    *(uint2*)(hi + i) = hp;
    *(uint2*)(lo + i) = lp;
}

// ===================== split-bf16 warp-MMA GEMM ============================
// C[M,N] = act(Ahi/lo[M,K] @ (Bhi/lo[N,K])^T + bias)
// BM=BN=128, BK=64. 16 warps (4 m x 4 n), warp tile 32x32.
// Smem: per stage 4 tiers (Ahi,Alo,Bhi,Blo), each 128 rows x 144B.
// 3-stage cp.async pipeline, one __syncthreads per stage.
#define ROW_BYTES   144u
#define TIER_BYTES  18432u           // 128 * 144
#define STAGE_BYTES 73728u           // 4 * TIER_BYTES
#define NSTAGE      3
#define GSMEM_SZ    (NSTAGE * 73728 + 1024)

template <int ACT, bool MINMAX, bool HASBIAS, bool SPLITOUT>
__global__ void __launch_bounds__(512, 1)
gemm_mma(const bf* __restrict__ Ahi, const bf* __restrict__ Alo,
         const bf* __restrict__ Bhi, const bf* __restrict__ Blo,
         const float* __restrict__ bias,
         float* __restrict__ Cf, bf* __restrict__ Chi, bf* __restrict__ Clo,
         int M, int N, int K)
{
    extern __shared__ char smem[];
    const uint32_t sb = smem_to_u32(smem);
    const int tid = threadIdx.x;
    const int wid = tid >> 5, lane = tid & 31;
    const int wm = wid & 3, wn = wid >> 2;        // 4 x 4 warps
    const int bm = blockIdx.y * 128, bn = blockIdx.x * 128;

    float* biasS = (float*)(smem + NSTAGE * STAGE_BYTES);
    if (HASBIAS && tid < 128) biasS[tid] = bias[bn + tid];

    // ldmatrix per-lane row-address offsets (within a tier)
    const int quad = lane >> 3, r8 = lane & 7;
    const uint32_t aoff = (uint32_t)((wm * 32 + (quad & 1) * 8 + r8) * ROW_BYTES
                                     + (quad >> 1) * 16);
    const uint32_t boff = (uint32_t)((wn * 32 + (quad >> 1) * 8 + r8) * ROW_BYTES
                                     + (quad & 1) * 16);

    float acc[2][4][4];
#pragma unroll
    for (int i = 0; i < 2; i++)
#pragma unroll
        for (int j = 0; j < 4; j++)
#pragma unroll
            for (int q = 0; q < 4; q++) acc[i][j][q] = 0.0f;

    const int T = K >> 6;

    auto load_stage = [&](int st, int k0) {
        const uint32_t base = sb + (uint32_t)st * STAGE_BYTES;
#pragma unroll
        for (int i = 0; i < 8; i++) {
            int id = tid + i * 512;              // 0..4095
            int tier = id >> 10;
            int rid = id & 1023;
            int row = rid >> 3, c = rid & 7;
            const bf* src;
            int rbase;
            if      (tier == 0) { src = Ahi; rbase = bm; }
            else if (tier == 1) { src = Alo; rbase = bm; }
            else if (tier == 2) { src = Bhi; rbase = bn; }
            else                { src = Blo; rbase = bn; }
            const bf* g = src + (size_t)(rbase + row) * K + k0 + c * 8;
            uint32_t d = base + (uint32_t)tier * TIER_BYTES
                         + (uint32_t)row * ROW_BYTES + (uint32_t)c * 16;
            CP_ASYNC16(d, g);
        }
        CP_COMMIT();
    };

    auto compute_stage = [&](int st) {
        const uint32_t base = sb + (uint32_t)st * STAGE_BYTES;
        const uint32_t Ah = base, Al = base + TIER_BYTES;
        const uint32_t Bh = base + 2 * TIER_BYTES, Bl = base + 3 * TIER_BYTES;
#pragma unroll
        for (int ks = 0; ks < 4; ks++) {
            const uint32_t ko = (uint32_t)ks * 32;
            uint32_t ah[2][4], al[2][4], bh[2][4], bl[2][4];
            LDSM_X4(ah[0][0], ah[0][1], ah[0][2], ah[0][3], Ah + aoff + ko);
            LDSM_X4(ah[1][0], ah[1][1], ah[1][2], ah[1][3], Ah + aoff + 2304 + ko);
            LDSM_X4(al[0][0], al[0][1], al[0][2], al[0][3], Al + aoff + ko);
            LDSM_X4(al[1][0], al[1][1], al[1][2], al[1][3], Al + aoff + 2304 + ko);
            LDSM_X4(bh[0][0], bh[0][1], bh[0][2], bh[0][3], Bh + boff + ko);
            LDSM_X4(bh[1][0], bh[1][1], bh[1][2], bh[1][3], Bh + boff + 2304 + ko);
            LDSM_X4(bl[0][0], bl[0][1], bl[0][2], bl[0][3], Bl + boff + ko);
            LDSM_X4(bl[1][0], bl[1][1], bl[1][2], bl[1][3], Bl + boff + 2304 + ko);
#pragma unroll
            for (int p = 0; p < 2; p++)
#pragma unroll
                for (int sub = 0; sub < 2; sub++) {
                    int nj = p * 2 + sub;
                    uint32_t h0 = bh[p][sub * 2], h1 = bh[p][sub * 2 + 1];
                    uint32_t l0 = bl[p][sub * 2], l1 = bl[p][sub * 2 + 1];
#pragma unroll
                    for (int mi = 0; mi < 2; mi++) {
                        mma_bf16(acc[mi][nj], ah[mi][0], ah[mi][1], ah[mi][2], ah[mi][3], h0, h1);
                        mma_bf16(acc[mi][nj], ah[mi][0], ah[mi][1], ah[mi][2], ah[mi][3], l0, l1);
                        mma_bf16(acc[mi][nj], al[mi][0], al[mi][1], al[mi][2], al[mi][3], h0, h1);
                    }
                }
        }
    };

    // prologue: 2 stages in flight
    load_stage(0, 0);
    load_stage(1, 64);
    for (int t = 0; t < T; t++) {
        if (t + 1 < T) CP_WAIT1(); else CP_WAIT0();
        __syncthreads();
        if (t + 2 < T) load_stage((t + 2) % NSTAGE, (t + 2) * 64);
        compute_stage(t % NSTAGE);
    }

    // ---------------- epilogue ----------------
    float lmin = INFINITY, lmax = -INFINITY;
    const int rbase = bm + wm * 32 + (lane >> 2);
    const int cloc0 = wn * 32 + (lane & 3) * 2;
#pragma unroll
    for (int mi = 0; mi < 2; mi++) {
#pragma unroll
        for (int nj = 0; nj < 4; nj++) {
            int cl = cloc0 + nj * 8;
            int n0 = bn + cl;
            float b0 = 0.f, b1 = 0.f;
            if (HASBIAS) { b0 = biasS[cl]; b1 = biasS[cl + 1]; }
#pragma unroll
            for (int h = 0; h < 2; h++) {
                int m = rbase + mi * 16 + h * 8;
                float v0 = apply_act(acc[mi][nj][h * 2 + 0] + b0, ACT);
                float v1 = apply_act(acc[mi][nj][h * 2 + 1] + b1, ACT);
                if (SPLITOUT) {
                    bf h0 = __float2bfloat16(v0), h1 = __float2bfloat16(v1);
                    bf q0 = __float2bfloat16(v0 - __bfloat162float(h0));
                    bf q1 = __float2bfloat16(v1 - __bfloat162float(h1));
                    uint32_t hw = (uint32_t)__bfloat16_as_ushort(h0) |
                                  ((uint32_t)__bfloat16_as_ushort(h1) << 16);
                    uint32_t lw = (uint32_t)__bfloat16_as_ushort(q0) |
                                  ((uint32_t)__bfloat16_as_ushort(q1) << 16);
                    *(uint32_t*)(Chi + (size_t)m * N + n0) = hw;
                    *(uint32_t*)(Clo + (size_t)m * N + n0) = lw;
                } else {
                    if (MINMAX) {
                        lmin = fminf(lmin, fminf(v0, v1));
                        lmax = fmaxf(lmax, fmaxf(v0, v1));
                    }
                    *(float2*)(Cf + (size_t)m * N + n0) = make_float2(v0, v1);
                }
            }
        }
    }

    if (MINMAX) {
        float* red = (float*)smem;   // stage memory is free now
        __syncthreads();
        red[tid] = lmin; red[512 + tid] = lmax;
        __syncthreads();
#pragma unroll
        for (int s = 256; s >= 64; s >>= 1) {
            if (tid < s) {
                red[tid] = fminf(red[tid], red[tid + s]);
                red[512 + tid] = fmaxf(red[512 + tid], red[512 + tid + s]);
            }
            __syncthreads();
        }
        if (tid < 32) {
            float a = fminf(red[tid], red[tid + 32]);
            float b = fmaxf(red[512 + tid], red[512 + tid + 32]);
#pragma unroll
            for (int o = 16; o > 0; o >>= 1) {
                a = fminf(a, __shfl_down_sync(0xffffffffu, a, o));
                b = fmaxf(b, __shfl_down_sync(0xffffffffu, b, o));
            }
            if (tid == 0) {
                atomicMin(&g_minkey, f2key(a));
                atomicMax(&g_maxkey, f2key(b));
            }
        }
    }
}

// ===================== N=1 projection from hi/lo bf16 ======================
template <int ACT>
__global__ void __launch_bounds__(256)
rowdot_bf(const bf* __restrict__ hi, const bf* __restrict__ lo,
          const float* __restrict__ w, const float* __restrict__ bias,
          float* __restrict__ out, int K)
{
    const int warp = threadIdx.x >> 5, lane = threadIdx.x & 31;
    const int row = blockIdx.x * 8 + warp;
    const bf* h = hi + (size_t)row * K;
    const bf* l = lo + (size_t)row * K;
    float s = 0.0f;
    for (int k = lane * 8; k < K; k += 32 * 8) {
        uint4 hv = *(const uint4*)(h + k);
        uint4 lv = *(const uint4*)(l + k);
        float4 w0 = *(const float4*)(w + k);
        float4 w1 = *(const float4*)(w + k + 4);
        const uint32_t hu[4] = {hv.x, hv.y, hv.z, hv.w};
        const uint32_t lu[4] = {lv.x, lv.y, lv.z, lv.w};
        const float wf[8] = {w0.x, w0.y, w0.z, w0.w, w1.x, w1.y, w1.z, w1.w};
#pragma unroll
        for (int q = 0; q < 4; q++) {
            __nv_bfloat162 h2 = *(const __nv_bfloat162*)&hu[q];
            __nv_bfloat162 l2 = *(const __nv_bfloat162*)&lu[q];
            s += (__low2float(h2) + __low2float(l2)) * wf[q * 2];
            s += (__high2float(h2) + __high2float(l2)) * wf[q * 2 + 1];
        }
    }
#pragma unroll
    for (int o = 16; o > 0; o >>= 1) s += __shfl_down_sync(0xffffffffu, s, o);
    if (lane == 0) out[row] = apply_act(s + bias[0], ACT);
}

// ===================== min/max init + final rescale ========================
__global__ void init_minmax_k() { g_minkey = 0xFFFFFFFFu; g_maxkey = 0u; }

__global__ void __launch_bounds__(256)
scale_out(const float* __restrict__ s, float* __restrict__ out)
{
    float mn = key2f(g_minkey);
    float mx = key2f(g_maxkey);
    float inv = 1.0f / (mx - mn);
    size_t i = ((size_t)blockIdx.x * blockDim.x + threadIdx.x) * 4;
    float4 v = *(const float4*)&s[i];
    float4 o;
    o.x = (v.x - mn) * inv; o.y = (v.y - mn) * inv;
    o.z = (v.z - mn) * inv; o.w = (v.w - mn) * inv;
    *(float4*)&out[i] = o;
}

// ===================== host launch =========================================
static void launch_gemm_act(int act, const bf* Ahi, const bf* Alo,
                            const bf* Bhi, const bf* Blo, const float* bias,
                            bf* Chi, bf* Clo, int M, int N, int K)
{
    dim3 grid(N / 128, M / 128), blk(512);
    if (act == ACT_RELU) {
        cudaFuncSetAttribute(gemm_mma<ACT_RELU, false, true, true>,
                             cudaFuncAttributeMaxDynamicSharedMemorySize, GSMEM_SZ);
        gemm_mma<ACT_RELU, false, true, true><<<grid, blk, GSMEM_SZ>>>(
            Ahi, Alo, Bhi, Blo, bias, nullptr, Chi, Clo, M, N, K);
    } else {
        cudaFuncSetAttribute(gemm_mma<ACT_SIG, false, true, true>,
                             cudaFuncAttributeMaxDynamicSharedMemorySize, GSMEM_SZ);
        gemm_mma<ACT_SIG, false, true, true><<<grid, blk, GSMEM_SZ>>>(
            Ahi, Alo, Bhi, Blo, bias, nullptr, Chi, Clo, M, N, K);
    }
}

extern "C" void kernel_launch(void* const* d_in, const int* in_sizes, int n_in,
                              void* d_out, int out_size)
{
    (void)in_sizes; (void)n_in; (void)out_size;
    const float* x1   = (const float*)d_in[0];
    const float* x2   = (const float*)d_in[1];
    const float* W1_1 = (const float*)d_in[2];   const float* b1_1 = (const float*)d_in[3];
    const float* W1_2 = (const float*)d_in[4];   const float* b1_2 = (const float*)d_in[5];
    const float* W1_3 = (const float*)d_in[6];   const float* b1_3 = (const float*)d_in[7];
    const float* W1_4 = (const float*)d_in[8];   const float* b1_4 = (const float*)d_in[9];
    const float* W1_5 = (const float*)d_in[10];  const float* b1_5 = (const float*)d_in[11];
    const float* Wp1  = (const float*)d_in[12];  const float* bp1  = (const float*)d_in[13];
    const float* W2_1 = (const float*)d_in[14];  const float* b2_1 = (const float*)d_in[15];
    const float* W2_2 = (const float*)d_in[16];  const float* b2_2 = (const float*)d_in[17];
    const float* W2_3 = (const float*)d_in[18];  const float* b2_3 = (const float*)d_in[19];
    const float* Wp2  = (const float*)d_in[20];  const float* bp2  = (const float*)d_in[21];

    float* out = (float*)d_out;
    const int B = 4096;
    const size_t NSC = (size_t)4096 * 4096;

    bf *ahi, *alo, *bhi, *blo, *x1h, *x1l, *x2h, *x2l, *whi, *wlo, *inh, *inl;
    float* scores;
    cudaGetSymbolAddress((void**)&ahi, g_ahi);    cudaGetSymbolAddress((void**)&alo, g_alo);
    cudaGetSymbolAddress((void**)&bhi, g_bhi);    cudaGetSymbolAddress((void**)&blo, g_blo);
    cudaGetSymbolAddress((void**)&x1h, g_x1v_hi); cudaGetSymbolAddress((void**)&x1l, g_x1v_lo);
    cudaGetSymbolAddress((void**)&x2h, g_x2v_hi); cudaGetSymbolAddress((void**)&x2l, g_x2v_lo);
    cudaGetSymbolAddress((void**)&whi, g_whi);    cudaGetSymbolAddress((void**)&wlo, g_wlo);
    cudaGetSymbolAddress((void**)&inh, g_inhi);   cudaGetSymbolAddress((void**)&inl, g_inlo);
    cudaGetSymbolAddress((void**)&scores, g_scores);

    init_minmax_k<<<1, 1>>>();

    // split inputs + weights into bf16 hi/lo
    struct { const float* p; unsigned off; int n; bool isw; } cv[10] = {
        {x1, OX1, 4194304, false}, {x2, OX2, 2097152, false},
        {W1_1, OW11, 2097152, true}, {W1_2, OW12, 2097152, true},
        {W1_3, OW13, 524288, true},  {W1_4, OW14, 524288, true},
        {W1_5, OW15, 2097152, true}, {W2_1, OW21, 524288, true},
        {W2_2, OW22, 524288, true},  {W2_3, OW23, 524288, true},
    };
    for (int i = 0; i < 10; i++) {
        bf* h = (cv[i].isw ? whi : inh) + cv[i].off;
        bf* l = (cv[i].isw ? wlo : inl) + cv[i].off;
        split_f32<<<cv[i].n / 1024, 256>>>(cv[i].p, h, l, cv[i].n);
    }

    // branch 1
    launch_gemm_act(ACT_RELU, inh + OX1, inl + OX1, whi + OW11, wlo + OW11, b1_1, ahi, alo, B, 2048, 1024);
    launch_gemm_act(ACT_RELU, ahi, alo, whi + OW12, wlo + OW12, b1_2, bhi, blo, B, 1024, 2048);
    launch_gemm_act(ACT_SIG,  bhi, blo, whi + OW13, wlo + OW13, b1_3, x1h, x1l, B, 512, 1024);
    launch_gemm_act(ACT_RELU, x1h, x1l, whi + OW14, wlo + OW14, b1_4, ahi, alo, B, 1024, 512);
    launch_gemm_act(ACT_RELU, ahi, alo, whi + OW15, wlo + OW15, b1_5, bhi, blo, B, 2048, 1024);
    rowdot_bf<ACT_SIG><<<B / 8, 256>>>(bhi, blo, Wp1, bp1, out + 0, 2048);            // pre_data

    // branch 2
    launch_gemm_act(ACT_RELU, inh + OX2, inl + OX2, whi + OW21, wlo + OW21, b2_1, ahi, alo, B, 1024, 512);
    launch_gemm_act(ACT_SIG,  ahi, alo, whi + OW22, wlo + OW22, b2_2, x2h, x2l, B, 512, 1024);
    launch_gemm_act(ACT_RELU, x2h, x2l, whi + OW23, wlo + OW23, b2_3, ahi, alo, B, 1024, 512);
    rowdot_bf<ACT_SIG><<<B / 8, 256>>>(ahi, alo, Wp2, bp2, out + 4096 + NSC, 1024);   // pre_model

    // cross scores with fused global min/max
    {
        dim3 grid(4096 / 128, B / 128), blk(512);
        cudaFuncSetAttribute(gemm_mma<ACT_NONE, true, false, false>,
                             cudaFuncAttributeMaxDynamicSharedMemorySize, GSMEM_SZ);
        gemm_mma<ACT_NONE, true, false, false><<<grid, blk, GSMEM_SZ>>>(
            x1h, x1l, x2h, x2l, nullptr, scores, nullptr, nullptr, B, 4096, 512);
    }

    // min-max rescale -> pre_dm
    scale_out<<<(unsigned)(NSC / 4 / 256), 256>>>(scores, out + 4096);
}

// round 6
// speedup vs baseline: 3.4835x; 1.4666x over previous
#include <cuda_runtime.h>
#include <cuda_fp16.h>
#include <math.h>
#include <stdint.h>

typedef __half hf;

// ===================== device scratch (no allocation allowed) ==============
__device__ hf g_actA[4096 * 2048];
__device__ hf g_actB[4096 * 2048];
__device__ hf g_x1v [4096 * 512];
__device__ hf g_x2v [4096 * 512];
__device__ hf g_wh  [8912896];
__device__ hf g_wl  [8912896];
__device__ hf g_in  [6291456];
__device__ float g_scores[(size_t)4096 * 4096];
__device__ unsigned g_minkey;
__device__ unsigned g_maxkey;

// weight pool offsets (elements)
#define OW11 0u
#define OW12 2097152u
#define OW13 4194304u
#define OW14 4718592u
#define OW15 5242880u
#define OW21 7340032u
#define OW22 7864320u
#define OW23 8388608u
#define OX1  0u
#define OX2  4194304u

#define WL_SCALE    2048.0f
#define WL_INVSCALE (1.0f / 2048.0f)

// ===================== PTX helpers =========================================
__device__ __forceinline__ uint32_t smem_to_u32(const void* p) {
    uint32_t a;
    asm("{ .reg .u64 t; cvta.to.shared.u64 t, %1; cvt.u32.u64 %0, t; }"
        : "=r"(a) : "l"(p));
    return a;
}

#define CP_ASYNC16(dst, src) \
    asm volatile("cp.async.cg.shared.global [%0], [%1], 16;" \
                 :: "r"(dst), "l"(src) : "memory")
#define CP_COMMIT() asm volatile("cp.async.commit_group;" ::: "memory")
#define CP_WAIT1()  asm volatile("cp.async.wait_group 1;" ::: "memory")
#define CP_WAIT0()  asm volatile("cp.async.wait_group 0;" ::: "memory")

#define LDSM_X4(r0, r1, r2, r3, addr) \
    asm volatile("ldmatrix.sync.aligned.m8n8.x4.shared.b16 {%0,%1,%2,%3}, [%4];" \
                 : "=r"(r0), "=r"(r1), "=r"(r2), "=r"(r3) : "r"(addr))

__device__ __forceinline__ void mma_f16(float* c, uint32_t a0, uint32_t a1,
                                        uint32_t a2, uint32_t a3,
                                        uint32_t b0, uint32_t b1) {
    asm volatile(
        "mma.sync.aligned.m16n8k16.row.col.f32.f16.f16.f32 "
        "{%0,%1,%2,%3}, {%4,%5,%6,%7}, {%8,%9}, {%0,%1,%2,%3};"
        : "+f"(c[0]), "+f"(c[1]), "+f"(c[2]), "+f"(c[3])
        : "r"(a0), "r"(a1), "r"(a2), "r"(a3), "r"(b0), "r"(b1));
}

// ===================== misc helpers ========================================
__device__ __forceinline__ unsigned f2key(float f) {
    unsigned u = __float_as_uint(f);
    return (u & 0x80000000u) ? ~u : (u | 0x80000000u);
}
__device__ __forceinline__ float key2f(unsigned k) {
    unsigned u = (k & 0x80000000u) ? (k ^ 0x80000000u) : ~k;
    return __uint_as_float(u);
}
enum { ACT_NONE = 0, ACT_RELU = 1, ACT_SIG = 2 };
__device__ __forceinline__ float apply_act(float v, int act) {
    if (act == ACT_RELU) return fmaxf(v, 0.0f);
    if (act == ACT_SIG)  return 1.0f / (1.0f + expf(-v));
    return v;
}

// ===================== conversions =========================================
// weights: fp32 -> fp16 hi + (residual * 2048) lo
__global__ void __launch_bounds__(256)
split_w(const float* __restrict__ in, hf* __restrict__ hi,
        hf* __restrict__ lo, int n)
{
    int i = (blockIdx.x * 256 + threadIdx.x) * 4;
    if (i >= n) return;
    float4 v = *(const float4*)(in + i);
    hf h0 = __float2half_rn(v.x), h1 = __float2half_rn(v.y);
    hf h2 = __float2half_rn(v.z), h3 = __float2half_rn(v.w);
    hf l0 = __float2half_rn((v.x - __half2float(h0)) * WL_SCALE);
    hf l1 = __float2half_rn((v.y - __half2float(h1)) * WL_SCALE);
    hf l2 = __float2half_rn((v.z - __half2float(h2)) * WL_SCALE);
    hf l3 = __float2half_rn((v.w - __half2float(h3)) * WL_SCALE);
    uint2 hp, lp;
    hp.x = (uint32_t)__half_as_ushort(h0) | ((uint32_t)__half_as_ushort(h1) << 16);
    hp.y = (uint32_t)__half_as_ushort(h2) | ((uint32_t)__half_as_ushort(h3) << 16);
    lp.x = (uint32_t)__half_as_ushort(l0) | ((uint32_t)__half_as_ushort(l1) << 16);
    lp.y = (uint32_t)__half_as_ushort(l2) | ((uint32_t)__half_as_ushort(l3) << 16);
    *(uint2*)(hi + i) = hp;
    *(uint2*)(lo + i) = lp;
}

// inputs: fp32 -> fp16
__global__ void __launch_bounds__(256)
conv_h(const float* __restrict__ in, hf* __restrict__ outp, int n)
{
    int i = (blockIdx.x * 256 + threadIdx.x) * 4;
    if (i >= n) return;
    float4 v = *(const float4*)(in + i);
    __half2 a = __floats2half2_rn(v.x, v.y);
    __half2 b = __floats2half2_rn(v.z, v.w);
    uint2 p;
    p.x = *(uint32_t*)&a; p.y = *(uint32_t*)&b;
    *(uint2*)(outp + i) = p;
}

// ===================== fp16 warp-MMA GEMM ==================================
// NTERMS==2: C = act(A @ (Wh + Wl/2048)^T + bias)   (A fp16, weights split)
// NTERMS==1: C = A @ B^T (both fp16) with fused global min/max -> fp32 out
// BM=BN=128, BK=64. 16 warps (4x4), warp tile 32x32. 3-stage cp.async.
#define ROW_BYTES   144u
#define TIER_BYTES  18432u           // 128 * 144
#define NSTAGE      3
#define GSMEM3      (NSTAGE * 3 * 18432 + 1024)
#define GSMEM2      (NSTAGE * 2 * 18432 + 1024)

template <int ACT, int NTERMS, bool OUTF>
__global__ void __launch_bounds__(512, 1)
gemm_mma(const hf* __restrict__ A, const hf* __restrict__ Bh_,
         const hf* __restrict__ Bl_, const float* __restrict__ bias,
         float* __restrict__ Cf, hf* __restrict__ Ch,
         int M, int N, int K)
{
    constexpr int NT = NTERMS + 1;                    // tiers per stage
    constexpr uint32_t STB = NT * TIER_BYTES;
    extern __shared__ char smem[];
    const uint32_t sb = smem_to_u32(smem);
    const int tid = threadIdx.x;
    const int wid = tid >> 5, lane = tid & 31;
    const int wm = wid & 3, wn = wid >> 2;
    const int bm = blockIdx.y * 128, bn = blockIdx.x * 128;

    float* biasS = (float*)(smem + NSTAGE * STB);
    if (!OUTF && tid < 128) biasS[tid] = bias[bn + tid];

    const int quad = lane >> 3, r8 = lane & 7;
    const uint32_t aoff = (uint32_t)((wm * 32 + (quad & 1) * 8 + r8) * ROW_BYTES
                                     + (quad >> 1) * 16);
    const uint32_t boff = (uint32_t)((wn * 32 + (quad >> 1) * 8 + r8) * ROW_BYTES
                                     + (quad & 1) * 16);

    float acc[2][4][4];
    float acc2[2][4][4];
#pragma unroll
    for (int i = 0; i < 2; i++)
#pragma unroll
        for (int j = 0; j < 4; j++)
#pragma unroll
            for (int q = 0; q < 4; q++) {
                acc[i][j][q] = 0.0f;
                if (NTERMS == 2) acc2[i][j][q] = 0.0f;
            }

    const int T = K >> 6;

    auto load_stage = [&](int st, int k0) {
        const uint32_t base = sb + (uint32_t)st * STB;
#pragma unroll
        for (int i = 0; i < NT * 2; i++) {
            int id = tid + i * 512;              // 0 .. NT*1024-1
            int tier = id >> 10;
            int rid = id & 1023;
            int row = rid >> 3, c = rid & 7;
            const hf* src = (tier == 0) ? A : (tier == 1) ? Bh_ : Bl_;
            int rbase = (tier == 0) ? bm : bn;
            const hf* g = src + (size_t)(rbase + row) * K + k0 + c * 8;
            uint32_t d = base + (uint32_t)tier * TIER_BYTES
                         + (uint32_t)row * ROW_BYTES + (uint32_t)c * 16;
            CP_ASYNC16(d, g);
        }
        CP_COMMIT();
    };

    auto compute_stage = [&](int st) {
        const uint32_t base = sb + (uint32_t)st * STB;
        const uint32_t Ah = base;
        const uint32_t Bh = base + TIER_BYTES;
        const uint32_t Bl = base + 2 * TIER_BYTES;
#pragma unroll
        for (int ks = 0; ks < 4; ks++) {
            const uint32_t ko = (uint32_t)ks * 32;
            uint32_t ah[2][4], bh[2][4], bl[2][4];
            LDSM_X4(ah[0][0], ah[0][1], ah[0][2], ah[0][3], Ah + aoff + ko);
            LDSM_X4(ah[1][0], ah[1][1], ah[1][2], ah[1][3], Ah + aoff + 2304 + ko);
            LDSM_X4(bh[0][0], bh[0][1], bh[0][2], bh[0][3], Bh + boff + ko);
            LDSM_X4(bh[1][0], bh[1][1], bh[1][2], bh[1][3], Bh + boff + 2304 + ko);
            if (NTERMS == 2) {
                LDSM_X4(bl[0][0], bl[0][1], bl[0][2], bl[0][3], Bl + boff + ko);
                LDSM_X4(bl[1][0], bl[1][1], bl[1][2], bl[1][3], Bl + boff + 2304 + ko);
            }
#pragma unroll
            for (int p = 0; p < 2; p++)
#pragma unroll
                for (int sub = 0; sub < 2; sub++) {
                    int nj = p * 2 + sub;
                    uint32_t h0 = bh[p][sub * 2], h1 = bh[p][sub * 2 + 1];
#pragma unroll
                    for (int mi = 0; mi < 2; mi++) {
                        mma_f16(acc[mi][nj], ah[mi][0], ah[mi][1], ah[mi][2], ah[mi][3], h0, h1);
                        if (NTERMS == 2)
                            mma_f16(acc2[mi][nj], ah[mi][0], ah[mi][1], ah[mi][2], ah[mi][3],
                                    bl[p][sub * 2], bl[p][sub * 2 + 1]);
                    }
                }
        }
    };

    load_stage(0, 0);
    load_stage(1, 64);
    for (int t = 0; t < T; t++) {
        if (t + 1 < T) CP_WAIT1(); else CP_WAIT0();
        __syncthreads();
        if (t + 2 < T) load_stage((t + 2) % NSTAGE, (t + 2) * 64);
        compute_stage(t % NSTAGE);
    }

    // ---------------- epilogue ----------------
    float lmin = INFINITY, lmax = -INFINITY;
    const int rbase = bm + wm * 32 + (lane >> 2);
    const int cloc0 = wn * 32 + (lane & 3) * 2;
#pragma unroll
    for (int mi = 0; mi < 2; mi++) {
#pragma unroll
        for (int nj = 0; nj < 4; nj++) {
            int cl = cloc0 + nj * 8;
            int n0 = bn + cl;
            float b0 = 0.f, b1 = 0.f;
            if (!OUTF) { b0 = biasS[cl]; b1 = biasS[cl + 1]; }
#pragma unroll
            for (int h = 0; h < 2; h++) {
                int m = rbase + mi * 16 + h * 8;
                float v0 = acc[mi][nj][h * 2 + 0];
                float v1 = acc[mi][nj][h * 2 + 1];
                if (NTERMS == 2) {
                    v0 += acc2[mi][nj][h * 2 + 0] * WL_INVSCALE;
                    v1 += acc2[mi][nj][h * 2 + 1] * WL_INVSCALE;
                }
                v0 = apply_act(v0 + b0, ACT);
                v1 = apply_act(v1 + b1, ACT);
                if (OUTF) {
                    lmin = fminf(lmin, fminf(v0, v1));
                    lmax = fmaxf(lmax, fmaxf(v0, v1));
                    *(float2*)(Cf + (size_t)m * N + n0) = make_float2(v0, v1);
                } else {
                    __half2 hv = __floats2half2_rn(v0, v1);
                    *(__half2*)(Ch + (size_t)m * N + n0) = hv;
                }
            }
        }
    }

    if (OUTF) {
        float* red = (float*)smem;   // stage memory is free now
        __syncthreads();
        red[tid] = lmin; red[512 + tid] = lmax;
        __syncthreads();
#pragma unroll
        for (int s = 256; s >= 64; s >>= 1) {
            if (tid < s) {
                red[tid] = fminf(red[tid], red[tid + s]);
                red[512 + tid] = fmaxf(red[512 + tid], red[512 + tid + s]);
            }
            __syncthreads();
        }
        if (tid < 32) {
            float a = fminf(red[tid], red[tid + 32]);
            float b = fmaxf(red[512 + tid], red[512 + tid + 32]);
#pragma unroll
            for (int o = 16; o > 0; o >>= 1) {
                a = fminf(a, __shfl_down_sync(0xffffffffu, a, o));
                b = fmaxf(b, __shfl_down_sync(0xffffffffu, b, o));
            }
            if (tid == 0) {
                atomicMin(&g_minkey, f2key(a));
                atomicMax(&g_maxkey, f2key(b));
            }
        }
    }
}

// ===================== N=1 projection from fp16 activations ================
template <int ACT>
__global__ void __launch_bounds__(256)
rowdot_h(const hf* __restrict__ act, const float* __restrict__ w,
         const float* __restrict__ bias, float* __restrict__ out, int K)
{
    const int warp = threadIdx.x >> 5, lane = threadIdx.x & 31;
    const int row = blockIdx.x * 8 + warp;
    const hf* a = act + (size_t)row * K;
    float s = 0.0f;
    for (int k = lane * 8; k < K; k += 32 * 8) {
        uint4 av = *(const uint4*)(a + k);
        float4 w0 = *(const float4*)(w + k);
        float4 w1 = *(const float4*)(w + k + 4);
        const uint32_t au[4] = {av.x, av.y, av.z, av.w};
        const float wf[8] = {w0.x, w0.y, w0.z, w0.w, w1.x, w1.y, w1.z, w1.w};
#pragma unroll
        for (int q = 0; q < 4; q++) {
            __half2 h2 = *(const __half2*)&au[q];
            s += __low2float(h2) * wf[q * 2];
            s += __high2float(h2) * wf[q * 2 + 1];
        }
    }
#pragma unroll
    for (int o = 16; o > 0; o >>= 1) s += __shfl_down_sync(0xffffffffu, s, o);
    if (lane == 0) out[row] = apply_act(s + bias[0], ACT);
}

// ===================== min/max init + final rescale ========================
__global__ void init_minmax_k() { g_minkey = 0xFFFFFFFFu; g_maxkey = 0u; }

__global__ void __launch_bounds__(256)
scale_out(const float* __restrict__ s, float* __restrict__ out)
{
    float mn = key2f(g_minkey);
    float mx = key2f(g_maxkey);
    float inv = 1.0f / (mx - mn);
    size_t i = ((size_t)blockIdx.x * blockDim.x + threadIdx.x) * 4;
    float4 v = *(const float4*)&s[i];
    float4 o;
    o.x = (v.x - mn) * inv; o.y = (v.y - mn) * inv;
    o.z = (v.z - mn) * inv; o.w = (v.w - mn) * inv;
    *(float4*)&out[i] = o;
}

// ===================== host launch =========================================
static void launch_layer(int act, const hf* A, const hf* Wh, const hf* Wl,
                         const float* bias, hf* C, int M, int N, int K)
{
    dim3 grid(N / 128, M / 128), blk(512);
    if (act == ACT_RELU) {
        cudaFuncSetAttribute(gemm_mma<ACT_RELU, 2, false>,
                             cudaFuncAttributeMaxDynamicSharedMemorySize, GSMEM3);
        gemm_mma<ACT_RELU, 2, false><<<grid, blk, GSMEM3>>>(
            A, Wh, Wl, bias, nullptr, C, M, N, K);
    } else {
        cudaFuncSetAttribute(gemm_mma<ACT_SIG, 2, false>,
                             cudaFuncAttributeMaxDynamicSharedMemorySize, GSMEM3);
        gemm_mma<ACT_SIG, 2, false><<<grid, blk, GSMEM3>>>(
            A, Wh, Wl, bias, nullptr, C, M, N, K);
    }
}

extern "C" void kernel_launch(void* const* d_in, const int* in_sizes, int n_in,
                              void* d_out, int out_size)
{
    (void)in_sizes; (void)n_in; (void)out_size;
    const float* x1   = (const float*)d_in[0];
    const float* x2   = (const float*)d_in[1];
    const float* W1_1 = (const float*)d_in[2];   const float* b1_1 = (const float*)d_in[3];
    const float* W1_2 = (const float*)d_in[4];   const float* b1_2 = (const float*)d_in[5];
    const float* W1_3 = (const float*)d_in[6];   const float* b1_3 = (const float*)d_in[7];
    const float* W1_4 = (const float*)d_in[8];   const float* b1_4 = (const float*)d_in[9];
    const float* W1_5 = (const float*)d_in[10];  const float* b1_5 = (const float*)d_in[11];
    const float* Wp1  = (const float*)d_in[12];  const float* bp1  = (const float*)d_in[13];
    const float* W2_1 = (const float*)d_in[14];  const float* b2_1 = (const float*)d_in[15];
    const float* W2_2 = (const float*)d_in[16];  const float* b2_2 = (const float*)d_in[17];
    const float* W2_3 = (const float*)d_in[18];  const float* b2_3 = (const float*)d_in[19];
    const float* Wp2  = (const float*)d_in[20];  const float* bp2  = (const float*)d_in[21];

    float* out = (float*)d_out;
    const int B = 4096;
    const size_t NSC = (size_t)4096 * 4096;

    hf *actA, *actB, *x1v, *x2v, *wh, *wl, *inp;
    float* scores;
    cudaGetSymbolAddress((void**)&actA, g_actA);
    cudaGetSymbolAddress((void**)&actB, g_actB);
    cudaGetSymbolAddress((void**)&x1v, g_x1v);
    cudaGetSymbolAddress((void**)&x2v, g_x2v);
    cudaGetSymbolAddress((void**)&wh, g_wh);
    cudaGetSymbolAddress((void**)&wl, g_wl);
    cudaGetSymbolAddress((void**)&inp, g_in);
    cudaGetSymbolAddress((void**)&scores, g_scores);

    init_minmax_k<<<1, 1>>>();

    // convert inputs to fp16, split weights to fp16 hi/lo
    conv_h<<<4194304 / 1024, 256>>>(x1, inp + OX1, 4194304);
    conv_h<<<2097152 / 1024, 256>>>(x2, inp + OX2, 2097152);
    struct { const float* p; unsigned off; int n; } wv[8] = {
        {W1_1, OW11, 2097152}, {W1_2, OW12, 2097152}, {W1_3, OW13, 524288},
        {W1_4, OW14, 524288},  {W1_5, OW15, 2097152}, {W2_1, OW21, 524288},
        {W2_2, OW22, 524288},  {W2_3, OW23, 524288},
    };
    for (int i = 0; i < 8; i++)
        split_w<<<wv[i].n / 1024, 256>>>(wv[i].p, wh + wv[i].off, wl + wv[i].off, wv[i].n);

    // branch 1
    launch_layer(ACT_RELU, inp + OX1, wh + OW11, wl + OW11, b1_1, actA, B, 2048, 1024);
    launch_layer(ACT_RELU, actA, wh + OW12, wl + OW12, b1_2, actB, B, 1024, 2048);
    launch_layer(ACT_SIG,  actB, wh + OW13, wl + OW13, b1_3, x1v,  B, 512, 1024);
    launch_layer(ACT_RELU, x1v,  wh + OW14, wl + OW14, b1_4, actA, B, 1024, 512);
    launch_layer(ACT_RELU, actA, wh + OW15, wl + OW15, b1_5, actB, B, 2048, 1024);
    rowdot_h<ACT_SIG><<<B / 8, 256>>>(actB, Wp1, bp1, out + 0, 2048);            // pre_data

    // branch 2
    launch_layer(ACT_RELU, inp + OX2, wh + OW21, wl + OW21, b2_1, actA, B, 1024, 512);
    launch_layer(ACT_SIG,  actA, wh + OW22, wl + OW22, b2_2, x2v, B, 512, 1024);
    launch_layer(ACT_RELU, x2v,  wh + OW23, wl + OW23, b2_3, actA, B, 1024, 512);
    rowdot_h<ACT_SIG><<<B / 8, 256>>>(actA, Wp2, bp2, out + 4096 + NSC, 1024);   // pre_model

    // cross scores (single-term fp16) with fused global min/max
    {
        dim3 grid(4096 / 128, B / 128), blk(512);
        cudaFuncSetAttribute(gemm_mma<ACT_NONE, 1, true>,
                             cudaFuncAttributeMaxDynamicSharedMemorySize, GSMEM2);
        gemm_mma<ACT_NONE, 1, true><<<grid, blk, GSMEM2>>>(
            x1v, x2v, nullptr, nullptr, scores, nullptr, B, 4096, 512);
    }

    // min-max rescale -> pre_dm
    scale_out<<<(unsigned)(NSC / 4 / 256), 256>>>(scores, out + 4096);
}

// round 7
// speedup vs baseline: 4.1443x; 1.1897x over previous
#include <cuda_runtime.h>
#include <cuda_fp16.h>
#include <math.h>
#include <stdint.h>

typedef __half hf;

// ===================== device scratch (no allocation allowed) ==============
__device__ hf g_actA[4096 * 2048];
__device__ hf g_actB[4096 * 2048];
__device__ hf g_actC[4096 * 1024];      // branch-2 private activations
__device__ hf g_x1v [4096 * 512];
__device__ hf g_x2v [4096 * 512];
__device__ hf g_wh  [8912896];
__device__ hf g_wl  [8912896];
__device__ hf g_in  [6291456];
__device__ float g_scores[(size_t)4096 * 4096];
__device__ unsigned g_minkey;
__device__ unsigned g_maxkey;

// weight pool offsets (elements)
#define OW11 0u
#define OW12 2097152u
#define OW13 4194304u
#define OW14 4718592u
#define OW15 5242880u
#define OW21 7340032u
#define OW22 7864320u
#define OW23 8388608u
#define OX1  0u
#define OX2  4194304u

#define WL_SCALE    2048.0f
#define WL_INVSCALE (1.0f / 2048.0f)

// ===================== PTX helpers =========================================
__device__ __forceinline__ uint32_t smem_to_u32(const void* p) {
    uint32_t a;
    asm("{ .reg .u64 t; cvta.to.shared.u64 t, %1; cvt.u32.u64 %0, t; }"
        : "=r"(a) : "l"(p));
    return a;
}

#define CP_ASYNC16(dst, src) \
    asm volatile("cp.async.cg.shared.global [%0], [%1], 16;" \
                 :: "r"(dst), "l"(src) : "memory")
#define CP_COMMIT() asm volatile("cp.async.commit_group;" ::: "memory")
#define CP_WAIT1()  asm volatile("cp.async.wait_group 1;" ::: "memory")
#define CP_WAIT0()  asm volatile("cp.async.wait_group 0;" ::: "memory")

#define LDSM_X4(r0, r1, r2, r3, addr) \
    asm volatile("ldmatrix.sync.aligned.m8n8.x4.shared.b16 {%0,%1,%2,%3}, [%4];" \
                 : "=r"(r0), "=r"(r1), "=r"(r2), "=r"(r3) : "r"(addr))

__device__ __forceinline__ void mma_f16(float* c, uint32_t a0, uint32_t a1,
                                        uint32_t a2, uint32_t a3,
                                        uint32_t b0, uint32_t b1) {
    asm volatile(
        "mma.sync.aligned.m16n8k16.row.col.f32.f16.f16.f32 "
        "{%0,%1,%2,%3}, {%4,%5,%6,%7}, {%8,%9}, {%0,%1,%2,%3};"
        : "+f"(c[0]), "+f"(c[1]), "+f"(c[2]), "+f"(c[3])
        : "r"(a0), "r"(a1), "r"(a2), "r"(a3), "r"(b0), "r"(b1));
}

// ===================== misc helpers ========================================
__device__ __forceinline__ unsigned f2key(float f) {
    unsigned u = __float_as_uint(f);
    return (u & 0x80000000u) ? ~u : (u | 0x80000000u);
}
__device__ __forceinline__ float key2f(unsigned k) {
    unsigned u = (k & 0x80000000u) ? (k ^ 0x80000000u) : ~k;
    return __uint_as_float(u);
}
enum { ACT_NONE = 0, ACT_RELU = 1, ACT_SIG = 2 };
__device__ __forceinline__ float apply_act(float v, int act) {
    if (act == ACT_RELU) return fmaxf(v, 0.0f);
    if (act == ACT_SIG)  return 1.0f / (1.0f + expf(-v));
    return v;
}

// ===================== conversions =========================================
__global__ void __launch_bounds__(256)
split_w(const float* __restrict__ in, hf* __restrict__ hi,
        hf* __restrict__ lo, int n)
{
    int i = (blockIdx.x * 256 + threadIdx.x) * 4;
    if (i >= n) return;
    float4 v = *(const float4*)(in + i);
    hf h0 = __float2half_rn(v.x), h1 = __float2half_rn(v.y);
    hf h2 = __float2half_rn(v.z), h3 = __float2half_rn(v.w);
    hf l0 = __float2half_rn((v.x - __half2float(h0)) * WL_SCALE);
    hf l1 = __float2half_rn((v.y - __half2float(h1)) * WL_SCALE);
    hf l2 = __float2half_rn((v.z - __half2float(h2)) * WL_SCALE);
    hf l3 = __float2half_rn((v.w - __half2float(h3)) * WL_SCALE);
    uint2 hp, lp;
    hp.x = (uint32_t)__half_as_ushort(h0) | ((uint32_t)__half_as_ushort(h1) << 16);
    hp.y = (uint32_t)__half_as_ushort(h2) | ((uint32_t)__half_as_ushort(h3) << 16);
    lp.x = (uint32_t)__half_as_ushort(l0) | ((uint32_t)__half_as_ushort(l1) << 16);
    lp.y = (uint32_t)__half_as_ushort(l2) | ((uint32_t)__half_as_ushort(l3) << 16);
    *(uint2*)(hi + i) = hp;
    *(uint2*)(lo + i) = lp;
}

__global__ void __launch_bounds__(256)
conv_h(const float* __restrict__ in, hf* __restrict__ outp, int n)
{
    int i = (blockIdx.x * 256 + threadIdx.x) * 4;
    if (i >= n) return;
    float4 v = *(const float4*)(in + i);
    __half2 a = __floats2half2_rn(v.x, v.y);
    __half2 b = __floats2half2_rn(v.z, v.w);
    uint2 p;
    p.x = *(uint32_t*)&a; p.y = *(uint32_t*)&b;
    *(uint2*)(outp + i) = p;
}

// ===================== fp16 warp-MMA GEMM ==================================
#define ROW_BYTES   144u
#define TIER_BYTES  18432u           // 128 * 144
#define NSTAGE      3
#define GSMEM3      (NSTAGE * 3 * 18432 + 1024)
#define GSMEM2      (NSTAGE * 2 * 18432 + 1024)

template <int ACT, int NTERMS, bool OUTF>
__global__ void __launch_bounds__(512, 1)
gemm_mma(const hf* __restrict__ A, const hf* __restrict__ Bh_,
         const hf* __restrict__ Bl_, const float* __restrict__ bias,
         float* __restrict__ Cf, hf* __restrict__ Ch,
         int M, int N, int K)
{
    constexpr int NT = NTERMS + 1;                    // tiers per stage
    constexpr uint32_t STB = NT * TIER_BYTES;
    extern __shared__ char smem[];
    const uint32_t sb = smem_to_u32(smem);
    const int tid = threadIdx.x;
    const int wid = tid >> 5, lane = tid & 31;
    const int wm = wid & 3, wn = wid >> 2;
    const int bm = blockIdx.y * 128, bn = blockIdx.x * 128;

    float* biasS = (float*)(smem + NSTAGE * STB);
    if (!OUTF && tid < 128) biasS[tid] = bias[bn + tid];

    const int quad = lane >> 3, r8 = lane & 7;
    const uint32_t aoff = (uint32_t)((wm * 32 + (quad & 1) * 8 + r8) * ROW_BYTES
                                     + (quad >> 1) * 16);
    const uint32_t boff = (uint32_t)((wn * 32 + (quad >> 1) * 8 + r8) * ROW_BYTES
                                     + (quad & 1) * 16);

    float acc[2][4][4];
    float acc2[2][4][4];
#pragma unroll
    for (int i = 0; i < 2; i++)
#pragma unroll
        for (int j = 0; j < 4; j++)
#pragma unroll
            for (int q = 0; q < 4; q++) {
                acc[i][j][q] = 0.0f;
                if (NTERMS == 2) acc2[i][j][q] = 0.0f;
            }

    const int T = K >> 6;

    auto load_stage = [&](int st, int k0) {
        const uint32_t base = sb + (uint32_t)st * STB;
#pragma unroll
        for (int i = 0; i < NT * 2; i++) {
            int id = tid + i * 512;
            int tier = id >> 10;
            int rid = id & 1023;
            int row = rid >> 3, c = rid & 7;
            const hf* src = (tier == 0) ? A : (tier == 1) ? Bh_ : Bl_;
            int rbase = (tier == 0) ? bm : bn;
            const hf* g = src + (size_t)(rbase + row) * K + k0 + c * 8;
            uint32_t d = base + (uint32_t)tier * TIER_BYTES
                         + (uint32_t)row * ROW_BYTES + (uint32_t)c * 16;
            CP_ASYNC16(d, g);
        }
        CP_COMMIT();
    };

    auto compute_stage = [&](int st) {
        const uint32_t base = sb + (uint32_t)st * STB;
        const uint32_t Ah = base;
        const uint32_t Bh = base + TIER_BYTES;
        const uint32_t Bl = base + 2 * TIER_BYTES;
#pragma unroll
        for (int ks = 0; ks < 4; ks++) {
            const uint32_t ko = (uint32_t)ks * 32;
            uint32_t ah[2][4], bh[2][4], bl[2][4];
            LDSM_X4(ah[0][0], ah[0][1], ah[0][2], ah[0][3], Ah + aoff + ko);
            LDSM_X4(ah[1][0], ah[1][1], ah[1][2], ah[1][3], Ah + aoff + 2304 + ko);
            LDSM_X4(bh[0][0], bh[0][1], bh[0][2], bh[0][3], Bh + boff + ko);
            LDSM_X4(bh[1][0], bh[1][1], bh[1][2], bh[1][3], Bh + boff + 2304 + ko);
            if (NTERMS == 2) {
                LDSM_X4(bl[0][0], bl[0][1], bl[0][2], bl[0][3], Bl + boff + ko);
                LDSM_X4(bl[1][0], bl[1][1], bl[1][2], bl[1][3], Bl + boff + 2304 + ko);
            }
#pragma unroll
            for (int p = 0; p < 2; p++)
#pragma unroll
                for (int sub = 0; sub < 2; sub++) {
                    int nj = p * 2 + sub;
                    uint32_t h0 = bh[p][sub * 2], h1 = bh[p][sub * 2 + 1];
#pragma unroll
                    for (int mi = 0; mi < 2; mi++) {
                        mma_f16(acc[mi][nj], ah[mi][0], ah[mi][1], ah[mi][2], ah[mi][3], h0, h1);
                        if (NTERMS == 2)
                            mma_f16(acc2[mi][nj], ah[mi][0], ah[mi][1], ah[mi][2], ah[mi][3],
                                    bl[p][sub * 2], bl[p][sub * 2 + 1]);
                    }
                }
        }
    };

    load_stage(0, 0);
    load_stage(1, 64);
    for (int t = 0; t < T; t++) {
        if (t + 1 < T) CP_WAIT1(); else CP_WAIT0();
        __syncthreads();
        if (t + 2 < T) load_stage((t + 2) % NSTAGE, (t + 2) * 64);
        compute_stage(t % NSTAGE);
    }

    // ---------------- epilogue ----------------
    float lmin = INFINITY, lmax = -INFINITY;
    const int rbase = bm + wm * 32 + (lane >> 2);
    const int cloc0 = wn * 32 + (lane & 3) * 2;
#pragma unroll
    for (int mi = 0; mi < 2; mi++) {
#pragma unroll
        for (int nj = 0; nj < 4; nj++) {
            int cl = cloc0 + nj * 8;
            int n0 = bn + cl;
            float b0 = 0.f, b1 = 0.f;
            if (!OUTF) { b0 = biasS[cl]; b1 = biasS[cl + 1]; }
#pragma unroll
            for (int h = 0; h < 2; h++) {
                int m = rbase + mi * 16 + h * 8;
                float v0 = acc[mi][nj][h * 2 + 0];
                float v1 = acc[mi][nj][h * 2 + 1];
                if (NTERMS == 2) {
                    v0 += acc2[mi][nj][h * 2 + 0] * WL_INVSCALE;
                    v1 += acc2[mi][nj][h * 2 + 1] * WL_INVSCALE;
                }
                v0 = apply_act(v0 + b0, ACT);
                v1 = apply_act(v1 + b1, ACT);
                if (OUTF) {
                    lmin = fminf(lmin, fminf(v0, v1));
                    lmax = fmaxf(lmax, fmaxf(v0, v1));
                    *(float2*)(Cf + (size_t)m * N + n0) = make_float2(v0, v1);
                } else {
                    __half2 hv = __floats2half2_rn(v0, v1);
                    *(__half2*)(Ch + (size_t)m * N + n0) = hv;
                }
            }
        }
    }

    if (OUTF) {
        float* red = (float*)smem;
        __syncthreads();
        red[tid] = lmin; red[512 + tid] = lmax;
        __syncthreads();
#pragma unroll
        for (int s = 256; s >= 64; s >>= 1) {
            if (tid < s) {
                red[tid] = fminf(red[tid], red[tid + s]);
                red[512 + tid] = fmaxf(red[512 + tid], red[512 + tid + s]);
            }
            __syncthreads();
        }
        if (tid < 32) {
            float a = fminf(red[tid], red[tid + 32]);
            float b = fmaxf(red[512 + tid], red[512 + tid + 32]);
#pragma unroll
            for (int o = 16; o > 0; o >>= 1) {
                a = fminf(a, __shfl_down_sync(0xffffffffu, a, o));
                b = fmaxf(b, __shfl_down_sync(0xffffffffu, b, o));
            }
            if (tid == 0) {
                atomicMin(&g_minkey, f2key(a));
                atomicMax(&g_maxkey, f2key(b));
            }
        }
    }
}

// ===================== N=1 projection from fp16 activations ================
template <int ACT>
__global__ void __launch_bounds__(256)
rowdot_h(const hf* __restrict__ act, const float* __restrict__ w,
         const float* __restrict__ bias, float* __restrict__ out, int K)
{
    const int warp = threadIdx.x >> 5, lane = threadIdx.x & 31;
    const int row = blockIdx.x * 8 + warp;
    const hf* a = act + (size_t)row * K;
    float s = 0.0f;
    for (int k = lane * 8; k < K; k += 32 * 8) {
        uint4 av = *(const uint4*)(a + k);
        float4 w0 = *(const float4*)(w + k);
        float4 w1 = *(const float4*)(w + k + 4);
        const uint32_t au[4] = {av.x, av.y, av.z, av.w};
        const float wf[8] = {w0.x, w0.y, w0.z, w0.w, w1.x, w1.y, w1.z, w1.w};
#pragma unroll
        for (int q = 0; q < 4; q++) {
            __half2 h2 = *(const __half2*)&au[q];
            s += __low2float(h2) * wf[q * 2];
            s += __high2float(h2) * wf[q * 2 + 1];
        }
    }
#pragma unroll
    for (int o = 16; o > 0; o >>= 1) s += __shfl_down_sync(0xffffffffu, s, o);
    if (lane == 0) out[row] = apply_act(s + bias[0], ACT);
}

// ===================== min/max init + final rescale ========================
__global__ void init_minmax_k() { g_minkey = 0xFFFFFFFFu; g_maxkey = 0u; }

__global__ void __launch_bounds__(256)
scale_out(const float* __restrict__ s, float* __restrict__ out)
{
    float mn = key2f(g_minkey);
    float mx = key2f(g_maxkey);
    float inv = 1.0f / (mx - mn);
    size_t i = ((size_t)blockIdx.x * blockDim.x + threadIdx.x) * 4;
    float4 v = *(const float4*)&s[i];
    float4 o;
    o.x = (v.x - mn) * inv; o.y = (v.y - mn) * inv;
    o.z = (v.z - mn) * inv; o.w = (v.w - mn) * inv;
    *(float4*)&out[i] = o;
}

// ===================== host launch =========================================
static void launch_layer(cudaStream_t st, int act, const hf* A, const hf* Wh,
                         const hf* Wl, const float* bias, hf* C,
                         int M, int N, int K)
{
    dim3 grid(N / 128, M / 128), blk(512);
    if (act == ACT_RELU) {
        cudaFuncSetAttribute(gemm_mma<ACT_RELU, 2, false>,
                             cudaFuncAttributeMaxDynamicSharedMemorySize, GSMEM3);
        gemm_mma<ACT_RELU, 2, false><<<grid, blk, GSMEM3, st>>>(
            A, Wh, Wl, bias, nullptr, C, M, N, K);
    } else {
        cudaFuncSetAttribute(gemm_mma<ACT_SIG, 2, false>,
                             cudaFuncAttributeMaxDynamicSharedMemorySize, GSMEM3);
        gemm_mma<ACT_SIG, 2, false><<<grid, blk, GSMEM3, st>>>(
            A, Wh, Wl, bias, nullptr, C, M, N, K);
    }
}

extern "C" void kernel_launch(void* const* d_in, const int* in_sizes, int n_in,
                              void* d_out, int out_size)
{
    (void)in_sizes; (void)n_in; (void)out_size;
    const float* x1   = (const float*)d_in[0];
    const float* x2   = (const float*)d_in[1];
    const float* W1_1 = (const float*)d_in[2];   const float* b1_1 = (const float*)d_in[3];
    const float* W1_2 = (const float*)d_in[4];   const float* b1_2 = (const float*)d_in[5];
    const float* W1_3 = (const float*)d_in[6];   const float* b1_3 = (const float*)d_in[7];
    const float* W1_4 = (const float*)d_in[8];   const float* b1_4 = (const float*)d_in[9];
    const float* W1_5 = (const float*)d_in[10];  const float* b1_5 = (const float*)d_in[11];
    const float* Wp1  = (const float*)d_in[12];  const float* bp1  = (const float*)d_in[13];
    const float* W2_1 = (const float*)d_in[14];  const float* b2_1 = (const float*)d_in[15];
    const float* W2_2 = (const float*)d_in[16];  const float* b2_2 = (const float*)d_in[17];
    const float* W2_3 = (const float*)d_in[18];  const float* b2_3 = (const float*)d_in[19];
    const float* Wp2  = (const float*)d_in[20];  const float* bp2  = (const float*)d_in[21];

    float* out = (float*)d_out;
    const int B = 4096;
    const size_t NSC = (size_t)4096 * 4096;

    hf *actA, *actB, *actC, *x1v, *x2v, *wh, *wl, *inp;
    float* scores;
    cudaGetSymbolAddress((void**)&actA, g_actA);
    cudaGetSymbolAddress((void**)&actB, g_actB);
    cudaGetSymbolAddress((void**)&actC, g_actC);
    cudaGetSymbolAddress((void**)&x1v, g_x1v);
    cudaGetSymbolAddress((void**)&x2v, g_x2v);
    cudaGetSymbolAddress((void**)&wh, g_wh);
    cudaGetSymbolAddress((void**)&wl, g_wl);
    cudaGetSymbolAddress((void**)&inp, g_in);
    cudaGetSymbolAddress((void**)&scores, g_scores);

    // streams/events created once (host-side only; no device allocation)
    static cudaStream_t s2 = nullptr, s3 = nullptr;
    static cudaEvent_t evFork = nullptr, evX1v = nullptr, evX2v = nullptr,
                       evB2 = nullptr, evS3 = nullptr;
    if (!s2) {
        cudaStreamCreateWithFlags(&s2, cudaStreamNonBlocking);
        cudaStreamCreateWithFlags(&s3, cudaStreamNonBlocking);
        cudaEventCreateWithFlags(&evFork, cudaEventDisableTiming);
        cudaEventCreateWithFlags(&evX1v,  cudaEventDisableTiming);
        cudaEventCreateWithFlags(&evX2v,  cudaEventDisableTiming);
        cudaEventCreateWithFlags(&evB2,   cudaEventDisableTiming);
        cudaEventCreateWithFlags(&evS3,   cudaEventDisableTiming);
    }

    // ---- stream0: init + fork ----
    init_minmax_k<<<1, 1>>>();
    cudaEventRecord(evFork, 0);
    cudaStreamWaitEvent(s2, evFork, 0);

    // ---- s2: branch 2 (independent of branch 1) ----
    conv_h<<<2097152 / 1024, 256, 0, s2>>>(x2, inp + OX2, 2097152);
    split_w<<<524288 / 1024, 256, 0, s2>>>(W2_1, wh + OW21, wl + OW21, 524288);
    split_w<<<524288 / 1024, 256, 0, s2>>>(W2_2, wh + OW22, wl + OW22, 524288);
    split_w<<<524288 / 1024, 256, 0, s2>>>(W2_3, wh + OW23, wl + OW23, 524288);
    launch_layer(s2, ACT_RELU, inp + OX2, wh + OW21, wl + OW21, b2_1, actC, B, 1024, 512);
    launch_layer(s2, ACT_SIG,  actC, wh + OW22, wl + OW22, b2_2, x2v, B, 512, 1024);
    cudaEventRecord(evX2v, s2);
    launch_layer(s2, ACT_RELU, x2v, wh + OW23, wl + OW23, b2_3, actC, B, 1024, 512);
    rowdot_h<ACT_SIG><<<B / 8, 256, 0, s2>>>(actC, Wp2, bp2, out + 4096 + NSC, 1024); // pre_model
    cudaEventRecord(evB2, s2);

    // ---- stream0: branch 1 ----
    conv_h<<<4194304 / 1024, 256>>>(x1, inp + OX1, 4194304);
    split_w<<<2097152 / 1024, 256>>>(W1_1, wh + OW11, wl + OW11, 2097152);
    split_w<<<2097152 / 1024, 256>>>(W1_2, wh + OW12, wl + OW12, 2097152);
    split_w<<<524288 / 1024, 256>>>(W1_3, wh + OW13, wl + OW13, 524288);
    split_w<<<524288 / 1024, 256>>>(W1_4, wh + OW14, wl + OW14, 524288);
    split_w<<<2097152 / 1024, 256>>>(W1_5, wh + OW15, wl + OW15, 2097152);

    launch_layer(0, ACT_RELU, inp + OX1, wh + OW11, wl + OW11, b1_1, actA, B, 2048, 1024);
    launch_layer(0, ACT_RELU, actA, wh + OW12, wl + OW12, b1_2, actB, B, 1024, 2048);
    launch_layer(0, ACT_SIG,  actB, wh + OW13, wl + OW13, b1_3, x1v,  B, 512, 1024);
    cudaEventRecord(evX1v, 0);
    launch_layer(0, ACT_RELU, x1v,  wh + OW14, wl + OW14, b1_4, actA, B, 1024, 512);
    launch_layer(0, ACT_RELU, actA, wh + OW15, wl + OW15, b1_5, actB, B, 2048, 1024);
    rowdot_h<ACT_SIG><<<B / 8, 256>>>(actB, Wp1, bp1, out + 0, 2048);             // pre_data

    // ---- s3: cross scores + rescale (overlaps B1 L4/L5) ----
    cudaStreamWaitEvent(s3, evX1v, 0);
    cudaStreamWaitEvent(s3, evX2v, 0);
    {
        dim3 grid(4096 / 128, B / 128), blk(512);
        cudaFuncSetAttribute(gemm_mma<ACT_NONE, 1, true>,
                             cudaFuncAttributeMaxDynamicSharedMemorySize, GSMEM2);
        gemm_mma<ACT_NONE, 1, true><<<grid, blk, GSMEM2, s3>>>(
            x1v, x2v, nullptr, nullptr, scores, nullptr, B, 4096, 512);
    }
    scale_out<<<(unsigned)(NSC / 4 / 256), 256, 0, s3>>>(scores, out + 4096);     // pre_dm
    cudaEventRecord(evS3, s3);

    // ---- join everything back into stream0 ----
    cudaStreamWaitEvent(0, evB2, 0);
    cudaStreamWaitEvent(0, evS3, 0);
}

// round 8
// speedup vs baseline: 5.7441x; 1.3860x over previous
#include <cuda_runtime.h>
#include <cuda_fp16.h>
#include <math.h>
#include <stdint.h>

typedef __half hf;

// ===================== device scratch (no allocation allowed) ==============
__device__ hf g_actA[4096 * 2048];
__device__ hf g_actB[4096 * 2048];
__device__ hf g_actC[4096 * 1024];      // branch-2 private activations
__device__ hf g_x1v [4096 * 512];
__device__ hf g_x2v [4096 * 512];
__device__ hf g_wh  [8912896];
__device__ hf g_in  [6291456];
__device__ float g_scores[(size_t)4096 * 4096];
__device__ unsigned g_minkey;
__device__ unsigned g_maxkey;

// weight pool offsets (elements)
#define OW11 0u
#define OW12 2097152u
#define OW13 4194304u
#define OW14 4718592u
#define OW15 5242880u
#define OW21 7340032u
#define OW22 7864320u
#define OW23 8388608u
#define OX1  0u
#define OX2  4194304u

// ===================== PTX helpers =========================================
__device__ __forceinline__ uint32_t smem_to_u32(const void* p) {
    uint32_t a;
    asm("{ .reg .u64 t; cvta.to.shared.u64 t, %1; cvt.u32.u64 %0, t; }"
        : "=r"(a) : "l"(p));
    return a;
}

#define CP_ASYNC16(dst, src) \
    asm volatile("cp.async.cg.shared.global [%0], [%1], 16;" \
                 :: "r"(dst), "l"(src) : "memory")
#define CP_COMMIT() asm volatile("cp.async.commit_group;" ::: "memory")
#define CP_WAIT1()  asm volatile("cp.async.wait_group 1;" ::: "memory")
#define CP_WAIT0()  asm volatile("cp.async.wait_group 0;" ::: "memory")

#define LDSM_X4(r0, r1, r2, r3, addr) \
    asm volatile("ldmatrix.sync.aligned.m8n8.x4.shared.b16 {%0,%1,%2,%3}, [%4];" \
                 : "=r"(r0), "=r"(r1), "=r"(r2), "=r"(r3) : "r"(addr))

__device__ __forceinline__ void mma_f16(float* c, uint32_t a0, uint32_t a1,
                                        uint32_t a2, uint32_t a3,
                                        uint32_t b0, uint32_t b1) {
    asm volatile(
        "mma.sync.aligned.m16n8k16.row.col.f32.f16.f16.f32 "
        "{%0,%1,%2,%3}, {%4,%5,%6,%7}, {%8,%9}, {%0,%1,%2,%3};"
        : "+f"(c[0]), "+f"(c[1]), "+f"(c[2]), "+f"(c[3])
        : "r"(a0), "r"(a1), "r"(a2), "r"(a3), "r"(b0), "r"(b1));
}

// ===================== misc helpers ========================================
__device__ __forceinline__ unsigned f2key(float f) {
    unsigned u = __float_as_uint(f);
    return (u & 0x80000000u) ? ~u : (u | 0x80000000u);
}
__device__ __forceinline__ float key2f(unsigned k) {
    unsigned u = (k & 0x80000000u) ? (k ^ 0x80000000u) : ~k;
    return __uint_as_float(u);
}
enum { ACT_NONE = 0, ACT_RELU = 1, ACT_SIG = 2 };
__device__ __forceinline__ float apply_act(float v, int act) {
    if (act == ACT_RELU) return fmaxf(v, 0.0f);
    if (act == ACT_SIG)  return 1.0f / (1.0f + expf(-v));
    return v;
}

// ===================== fp32 -> fp16 conversion =============================
__global__ void __launch_bounds__(256)
conv_h(const float* __restrict__ in, hf* __restrict__ outp, int n)
{
    int i = (blockIdx.x * 256 + threadIdx.x) * 4;
    if (i >= n) return;
    float4 v = *(const float4*)(in + i);
    __half2 a = __floats2half2_rn(v.x, v.y);
    __half2 b = __floats2half2_rn(v.z, v.w);
    uint2 p;
    p.x = *(uint32_t*)&a; p.y = *(uint32_t*)&b;
    *(uint2*)(outp + i) = p;
}

// ===================== fp16 warp-MMA GEMM ==================================
// C = act(A[M,K] @ B[N,K]^T + bias); A,B fp16, fp32 accumulate.
// BM=BN=128, BK=64. 16 warps (4x4), warp tile 32x32. 3-stage cp.async.
#define ROW_BYTES   144u
#define TIER_BYTES  18432u           // 128 * 144
#define NSTAGE      3
#define GSMEM2      (NSTAGE * 2 * 18432 + 1024)

template <int ACT, bool OUTF>
__global__ void __launch_bounds__(512, 1)
gemm_mma(const hf* __restrict__ A, const hf* __restrict__ Bm,
         const float* __restrict__ bias,
         float* __restrict__ Cf, hf* __restrict__ Ch,
         int M, int N, int K)
{
    constexpr uint32_t STB = 2 * TIER_BYTES;
    extern __shared__ char smem[];
    const uint32_t sb = smem_to_u32(smem);
    const int tid = threadIdx.x;
    const int wid = tid >> 5, lane = tid & 31;
    const int wm = wid & 3, wn = wid >> 2;
    const int bm = blockIdx.y * 128, bn = blockIdx.x * 128;

    float* biasS = (float*)(smem + NSTAGE * STB);
    if (!OUTF && tid < 128) biasS[tid] = bias[bn + tid];

    const int quad = lane >> 3, r8 = lane & 7;
    const uint32_t aoff = (uint32_t)((wm * 32 + (quad & 1) * 8 + r8) * ROW_BYTES
                                     + (quad >> 1) * 16);
    const uint32_t boff = (uint32_t)((wn * 32 + (quad >> 1) * 8 + r8) * ROW_BYTES
                                     + (quad & 1) * 16);

    float acc[2][4][4];
#pragma unroll
    for (int i = 0; i < 2; i++)
#pragma unroll
        for (int j = 0; j < 4; j++)
#pragma unroll
            for (int q = 0; q < 4; q++) acc[i][j][q] = 0.0f;

    const int T = K >> 6;

    auto load_stage = [&](int st, int k0) {
        const uint32_t base = sb + (uint32_t)st * STB;
#pragma unroll
        for (int i = 0; i < 4; i++) {
            int id = tid + i * 512;              // 0..2047
            int tier = id >> 10;
            int rid = id & 1023;
            int row = rid >> 3, c = rid & 7;
            const hf* src = (tier == 0) ? A : Bm;
            int rbase = (tier == 0) ? bm : bn;
            const hf* g = src + (size_t)(rbase + row) * K + k0 + c * 8;
            uint32_t d = base + (uint32_t)tier * TIER_BYTES
                         + (uint32_t)row * ROW_BYTES + (uint32_t)c * 16;
            CP_ASYNC16(d, g);
        }
        CP_COMMIT();
    };

    auto compute_stage = [&](int st) {
        const uint32_t base = sb + (uint32_t)st * STB;
        const uint32_t Ah = base;
        const uint32_t Bh = base + TIER_BYTES;
#pragma unroll
        for (int ks = 0; ks < 4; ks++) {
            const uint32_t ko = (uint32_t)ks * 32;
            uint32_t ah[2][4], bh[2][4];
            LDSM_X4(ah[0][0], ah[0][1], ah[0][2], ah[0][3], Ah + aoff + ko);
            LDSM_X4(ah[1][0], ah[1][1], ah[1][2], ah[1][3], Ah + aoff + 2304 + ko);
            LDSM_X4(bh[0][0], bh[0][1], bh[0][2], bh[0][3], Bh + boff + ko);
            LDSM_X4(bh[1][0], bh[1][1], bh[1][2], bh[1][3], Bh + boff + 2304 + ko);
#pragma unroll
            for (int p = 0; p < 2; p++)
#pragma unroll
                for (int sub = 0; sub < 2; sub++) {
                    int nj = p * 2 + sub;
                    uint32_t h0 = bh[p][sub * 2], h1 = bh[p][sub * 2 + 1];
#pragma unroll
                    for (int mi = 0; mi < 2; mi++)
                        mma_f16(acc[mi][nj], ah[mi][0], ah[mi][1], ah[mi][2], ah[mi][3], h0, h1);
                }
        }
    };

    load_stage(0, 0);
    load_stage(1, 64);
    for (int t = 0; t < T; t++) {
        if (t + 1 < T) CP_WAIT1(); else CP_WAIT0();
        __syncthreads();
        if (t + 2 < T) load_stage((t + 2) % NSTAGE, (t + 2) * 64);
        compute_stage(t % NSTAGE);
    }

    // ---------------- epilogue ----------------
    float lmin = INFINITY, lmax = -INFINITY;
    const int rbase = bm + wm * 32 + (lane >> 2);
    const int cloc0 = wn * 32 + (lane & 3) * 2;
#pragma unroll
    for (int mi = 0; mi < 2; mi++) {
#pragma unroll
        for (int nj = 0; nj < 4; nj++) {
            int cl = cloc0 + nj * 8;
            int n0 = bn + cl;
            float b0 = 0.f, b1 = 0.f;
            if (!OUTF) { b0 = biasS[cl]; b1 = biasS[cl + 1]; }
#pragma unroll
            for (int h = 0; h < 2; h++) {
                int m = rbase + mi * 16 + h * 8;
                float v0 = apply_act(acc[mi][nj][h * 2 + 0] + b0, ACT);
                float v1 = apply_act(acc[mi][nj][h * 2 + 1] + b1, ACT);
                if (OUTF) {
                    lmin = fminf(lmin, fminf(v0, v1));
                    lmax = fmaxf(lmax, fmaxf(v0, v1));
                    *(float2*)(Cf + (size_t)m * N + n0) = make_float2(v0, v1);
                } else {
                    __half2 hv = __floats2half2_rn(v0, v1);
                    *(__half2*)(Ch + (size_t)m * N + n0) = hv;
                }
            }
        }
    }

    if (OUTF) {
        float* red = (float*)smem;
        __syncthreads();
        red[tid] = lmin; red[512 + tid] = lmax;
        __syncthreads();
#pragma unroll
        for (int s = 256; s >= 64; s >>= 1) {
            if (tid < s) {
                red[tid] = fminf(red[tid], red[tid + s]);
                red[512 + tid] = fmaxf(red[512 + tid], red[512 + tid + s]);
            }
            __syncthreads();
        }
        if (tid < 32) {
            float a = fminf(red[tid], red[tid + 32]);
            float b = fmaxf(red[512 + tid], red[512 + tid + 32]);
#pragma unroll
            for (int o = 16; o > 0; o >>= 1) {
                a = fminf(a, __shfl_down_sync(0xffffffffu, a, o));
                b = fmaxf(b, __shfl_down_sync(0xffffffffu, b, o));
            }
            if (tid == 0) {
                atomicMin(&g_minkey, f2key(a));
                atomicMax(&g_maxkey, f2key(b));
            }
        }
    }
}

// ===================== N=1 projection from fp16 activations ================
template <int ACT>
__global__ void __launch_bounds__(256)
rowdot_h(const hf* __restrict__ act, const float* __restrict__ w,
         const float* __restrict__ bias, float* __restrict__ out, int K)
{
    const int warp = threadIdx.x >> 5, lane = threadIdx.x & 31;
    const int row = blockIdx.x * 8 + warp;
    const hf* a = act + (size_t)row * K;
    float s = 0.0f;
    for (int k = lane * 8; k < K; k += 32 * 8) {
        uint4 av = *(const uint4*)(a + k);
        float4 w0 = *(const float4*)(w + k);
        float4 w1 = *(const float4*)(w + k + 4);
        const uint32_t au[4] = {av.x, av.y, av.z, av.w};
        const float wf[8] = {w0.x, w0.y, w0.z, w0.w, w1.x, w1.y, w1.z, w1.w};
#pragma unroll
        for (int q = 0; q < 4; q++) {
            __half2 h2 = *(const __half2*)&au[q];
            s += __low2float(h2) * wf[q * 2];
            s += __high2float(h2) * wf[q * 2 + 1];
        }
    }
#pragma unroll
    for (int o = 16; o > 0; o >>= 1) s += __shfl_down_sync(0xffffffffu, s, o);
    if (lane == 0) out[row] = apply_act(s + bias[0], ACT);
}

// ===================== min/max init + final rescale ========================
__global__ void init_minmax_k() { g_minkey = 0xFFFFFFFFu; g_maxkey = 0u; }

__global__ void __launch_bounds__(256)
scale_out(const float* __restrict__ s, float* __restrict__ out)
{
    float mn = key2f(g_minkey);
    float mx = key2f(g_maxkey);
    float inv = 1.0f / (mx - mn);
    size_t i = ((size_t)blockIdx.x * blockDim.x + threadIdx.x) * 4;
    float4 v = *(const float4*)&s[i];
    float4 o;
    o.x = (v.x - mn) * inv; o.y = (v.y - mn) * inv;
    o.z = (v.z - mn) * inv; o.w = (v.w - mn) * inv;
    *(float4*)&out[i] = o;
}

// ===================== host launch =========================================
static void launch_layer(cudaStream_t st, int act, const hf* A, const hf* W,
                         const float* bias, hf* C, int M, int N, int K)
{
    dim3 grid(N / 128, M / 128), blk(512);
    if (act == ACT_RELU) {
        cudaFuncSetAttribute(gemm_mma<ACT_RELU, false>,
                             cudaFuncAttributeMaxDynamicSharedMemorySize, GSMEM2);
        gemm_mma<ACT_RELU, false><<<grid, blk, GSMEM2, st>>>(
            A, W, bias, nullptr, C, M, N, K);
    } else {
        cudaFuncSetAttribute(gemm_mma<ACT_SIG, false>,
                             cudaFuncAttributeMaxDynamicSharedMemorySize, GSMEM2);
        gemm_mma<ACT_SIG, false><<<grid, blk, GSMEM2, st>>>(
            A, W, bias, nullptr, C, M, N, K);
    }
}

extern "C" void kernel_launch(void* const* d_in, const int* in_sizes, int n_in,
                              void* d_out, int out_size)
{
    (void)in_sizes; (void)n_in; (void)out_size;
    const float* x1   = (const float*)d_in[0];
    const float* x2   = (const float*)d_in[1];
    const float* W1_1 = (const float*)d_in[2];   const float* b1_1 = (const float*)d_in[3];
    const float* W1_2 = (const float*)d_in[4];   const float* b1_2 = (const float*)d_in[5];
    const float* W1_3 = (const float*)d_in[6];   const float* b1_3 = (const float*)d_in[7];
    const float* W1_4 = (const float*)d_in[8];   const float* b1_4 = (const float*)d_in[9];
    const float* W1_5 = (const float*)d_in[10];  const float* b1_5 = (const float*)d_in[11];
    const float* Wp1  = (const float*)d_in[12];  const float* bp1  = (const float*)d_in[13];
    const float* W2_1 = (const float*)d_in[14];  const float* b2_1 = (const float*)d_in[15];
    const float* W2_2 = (const float*)d_in[16];  const float* b2_2 = (const float*)d_in[17];
    const float* W2_3 = (const float*)d_in[18];  const float* b2_3 = (const float*)d_in[19];
    const float* Wp2  = (const float*)d_in[20];  const float* bp2  = (const float*)d_in[21];

    float* out = (float*)d_out;
    const int B = 4096;
    const size_t NSC = (size_t)4096 * 4096;

    hf *actA, *actB, *actC, *x1v, *x2v, *wh, *inp;
    float* scores;
    cudaGetSymbolAddress((void**)&actA, g_actA);
    cudaGetSymbolAddress((void**)&actB, g_actB);
    cudaGetSymbolAddress((void**)&actC, g_actC);
    cudaGetSymbolAddress((void**)&x1v, g_x1v);
    cudaGetSymbolAddress((void**)&x2v, g_x2v);
    cudaGetSymbolAddress((void**)&wh, g_wh);
    cudaGetSymbolAddress((void**)&inp, g_in);
    cudaGetSymbolAddress((void**)&scores, g_scores);

    // streams/events created once (host-side only; no device allocation)
    static cudaStream_t s2 = nullptr, s3 = nullptr;
    static cudaEvent_t evFork = nullptr, evX1v = nullptr, evX2v = nullptr,
                       evB2 = nullptr, evS3 = nullptr;
    if (!s2) {
        cudaStreamCreateWithFlags(&s2, cudaStreamNonBlocking);
        cudaStreamCreateWithFlags(&s3, cudaStreamNonBlocking);
        cudaEventCreateWithFlags(&evFork, cudaEventDisableTiming);
        cudaEventCreateWithFlags(&evX1v,  cudaEventDisableTiming);
        cudaEventCreateWithFlags(&evX2v,  cudaEventDisableTiming);
        cudaEventCreateWithFlags(&evB2,   cudaEventDisableTiming);
        cudaEventCreateWithFlags(&evS3,   cudaEventDisableTiming);
    }

    // ---- stream0: init + fork ----
    init_minmax_k<<<1, 1>>>();
    cudaEventRecord(evFork, 0);
    cudaStreamWaitEvent(s2, evFork, 0);

    // ---- s2: branch 2 (independent of branch 1) ----
    conv_h<<<2097152 / 1024, 256, 0, s2>>>(x2, inp + OX2, 2097152);
    conv_h<<<524288 / 1024, 256, 0, s2>>>(W2_1, wh + OW21, 524288);
    conv_h<<<524288 / 1024, 256, 0, s2>>>(W2_2, wh + OW22, 524288);
    conv_h<<<524288 / 1024, 256, 0, s2>>>(W2_3, wh + OW23, 524288);
    launch_layer(s2, ACT_RELU, inp + OX2, wh + OW21, b2_1, actC, B, 1024, 512);
    launch_layer(s2, ACT_SIG,  actC, wh + OW22, b2_2, x2v, B, 512, 1024);
    cudaEventRecord(evX2v, s2);
    launch_layer(s2, ACT_RELU, x2v, wh + OW23, b2_3, actC, B, 1024, 512);
    rowdot_h<ACT_SIG><<<B / 8, 256, 0, s2>>>(actC, Wp2, bp2, out + 4096 + NSC, 1024); // pre_model
    cudaEventRecord(evB2, s2);

    // ---- stream0: branch 1 ----
    conv_h<<<4194304 / 1024, 256>>>(x1, inp + OX1, 4194304);
    conv_h<<<2097152 / 1024, 256>>>(W1_1, wh + OW11, 2097152);
    conv_h<<<2097152 / 1024, 256>>>(W1_2, wh + OW12, 2097152);
    conv_h<<<524288 / 1024, 256>>>(W1_3, wh + OW13, 524288);
    conv_h<<<524288 / 1024, 256>>>(W1_4, wh + OW14, 524288);
    conv_h<<<2097152 / 1024, 256>>>(W1_5, wh + OW15, 2097152);

    launch_layer(0, ACT_RELU, inp + OX1, wh + OW11, b1_1, actA, B, 2048, 1024);
    launch_layer(0, ACT_RELU, actA, wh + OW12, b1_2, actB, B, 1024, 2048);
    launch_layer(0, ACT_SIG,  actB, wh + OW13, b1_3, x1v,  B, 512, 1024);
    cudaEventRecord(evX1v, 0);
    launch_layer(0, ACT_RELU, x1v,  wh + OW14, b1_4, actA, B, 1024, 512);
    launch_layer(0, ACT_RELU, actA, wh + OW15, b1_5, actB, B, 2048, 1024);
    rowdot_h<ACT_SIG><<<B / 8, 256>>>(actB, Wp1, bp1, out + 0, 2048);             // pre_data

    // ---- s3: cross scores + rescale (overlaps B1 L4/L5) ----
    cudaStreamWaitEvent(s3, evX1v, 0);
    cudaStreamWaitEvent(s3, evX2v, 0);
    {
        dim3 grid(4096 / 128, B / 128), blk(512);
        cudaFuncSetAttribute(gemm_mma<ACT_NONE, true>,
                             cudaFuncAttributeMaxDynamicSharedMemorySize, GSMEM2);
        gemm_mma<ACT_NONE, true><<<grid, blk, GSMEM2, s3>>>(
            x1v, x2v, nullptr, scores, nullptr, B, 4096, 512);
    }
    scale_out<<<(unsigned)(NSC / 4 / 256), 256, 0, s3>>>(scores, out + 4096);     // pre_dm
    cudaEventRecord(evS3, s3);

    // ---- join everything back into stream0 ----
    cudaStreamWaitEvent(0, evB2, 0);
    cudaStreamWaitEvent(0, evS3, 0);
}